// round 11
// baseline (speedup 1.0000x reference)
#include <cuda_runtime.h>
#include <cuda_bf16.h>
#include <cstdint>

#define B_  16
#define S_  64
#define T_  64
#define E_  256
#define H_  512
#define VS_ 32000
#define MM_ 100
#define J_  201
#define BT_ (B_*T_)
#define G4_ (4*H_)

__device__ float d_x[BT_*E_];
__device__ float d_xrev[BT_*E_];
__device__ float d_gpre_fw[BT_*G4_];    // permuted gate layout
__device__ float d_gpre_bw[BT_*G4_];
__device__ float d_hstate[2*B_*H_];
__device__ float d_cstate[2*B_*H_];
__device__ float d_hcat[BT_*2*H_];
__device__ float d_logits[(size_t)BT_*VS_];
__device__ float d_rowmax[BT_];
__device__ float d_rowsum[BT_];
__device__ float d_nullstate[H_];
__device__ float d_nulllog[VS_];
__device__ float d_nullred[2];
__device__ float d_tmpt[BT_*E_];
__device__ float d_tt[BT_*H_];
__device__ float d_jl[BT_*J_];
__device__ float d_p0v[BT_];
__device__ __nv_bfloat16 d_tsb[BT_*H_];
__device__ __nv_bfloat16 d_wvT[(size_t)VS_*H_];
__device__ float d_whP[2*H_*G4_];       // [dir][k][c] permuted: c = h*4+g
__device__ float d_wxP[2*E_*G4_];       // [dir][e][c]
__device__ float d_bP[2*G4_];

__device__ __forceinline__ float sigmf(float x){ return 1.f/(1.f+expf(-x)); }
__device__ __forceinline__ uint32_t f2tf32(float v){
    uint32_t r; asm("cvt.rna.tf32.f32 %0, %1;" : "=r"(r) : "f"(v)); return r;
}

__global__ void k_init(){
    int i = blockIdx.x*blockDim.x + threadIdx.x;
    if (i < 2*B_*H_){ d_hstate[i]=0.f; d_cstate[i]=0.f; }
}

__global__ void k_embed(const int* __restrict__ targets, const int* __restrict__ lengths,
                        const float* __restrict__ emb){
    int bt = blockIdx.x, b = bt/T_, t = bt%T_;
    int len = lengths[b];
    int rt = (t < len) ? (len-1-t) : t;
    int r0 = targets[bt], r1 = targets[b*T_+rt];
    for (int e = threadIdx.x; e < E_; e += blockDim.x){
        d_x[bt*E_+e]    = emb[(size_t)r0*E_+e];
        d_xrev[bt*E_+e] = emb[(size_t)r1*E_+e];
    }
}

__global__ void k_nullstate(const int* __restrict__ tnull, const float* __restrict__ emb,
                            const float* __restrict__ nnW, const float* __restrict__ nnb){
    __shared__ float xe[E_];
    int tid = threadIdx.x;          // 512
    int r = tnull[0];
    for (int e = tid; e < E_; e += blockDim.x) xe[e] = emb[(size_t)r*E_+e];
    __syncthreads();
    float a = nnb[tid];
    #pragma unroll 4
    for (int e = 0; e < E_; e++) a = fmaf(xe[e], nnW[e*H_+tid], a);
    d_nullstate[tid] = tanhf(a);
}

// permute LSTM weights to gate-interleaved layout: c = h*4+g  <-  g*H+h
__global__ void k_permw(const float* __restrict__ Wxf, const float* __restrict__ Wxb,
                        const float* __restrict__ bf,  const float* __restrict__ bb,
                        const float* __restrict__ Whf, const float* __restrict__ Whb){
    int stride = gridDim.x*blockDim.x;
    int base = blockIdx.x*blockDim.x + threadIdx.x;
    for (int i = base; i < 2*H_*G4_; i += stride){
        int dir = i / (H_*G4_); int r = (i >> 11) & (H_-1); int c = i & (G4_-1);
        int g = c & 3, h = c >> 2;
        d_whP[i] = (dir ? Whb : Whf)[(size_t)r*G4_ + g*H_ + h];
    }
    for (int i = base; i < 2*E_*G4_; i += stride){
        int dir = i / (E_*G4_); int r = (i >> 11) & (E_-1); int c = i & (G4_-1);
        int g = c & 3, h = c >> 2;
        d_wxP[i] = (dir ? Wxb : Wxf)[(size_t)r*G4_ + g*H_ + h];
    }
    for (int i = base; i < 2*G4_; i += stride){
        int dir = i / G4_; int c = i & (G4_-1);
        int g = c & 3, h = c >> 2;
        d_bP[i] = (dir ? bb : bf)[g*H_ + h];
    }
}

// transpose+convert Wv [H,VS] fp32 -> d_wvT [VS,H] bf16
__global__ void k_cvt_wvT(const float* __restrict__ Wv){
    __shared__ float tile[32][33];
    int nb = blockIdx.x, kb = blockIdx.y;
    int tx = threadIdx.x, ty = threadIdx.y;   // 32 x 8
    #pragma unroll
    for (int i = 0; i < 32; i += 8)
        tile[ty+i][tx] = Wv[(size_t)(kb*32+ty+i)*VS_ + nb*32+tx];
    __syncthreads();
    #pragma unroll
    for (int i = 0; i < 32; i += 8)
        d_wvT[(size_t)(nb*32+ty+i)*H_ + kb*32+tx] = __float2bfloat16(tile[tx][ty+i]);
}

#define CP_ASYNC16(dst, src) \
    asm volatile("cp.async.cg.shared.global [%0], [%1], 16;\n" :: "r"(dst), "l"(src))
#define CP_COMMIT() asm volatile("cp.async.commit_group;\n" ::: "memory")
#define CP_WAIT(n)  asm volatile("cp.async.wait_group %0;\n" :: "n"(n) : "memory")

// ---------------- bf16 mma.sync GEMM (unchanged from R10) ----------------
__global__ void __launch_bounds__(256) bf16gemm_k(const __nv_bfloat16* __restrict__ A,
                                                  const __nv_bfloat16* __restrict__ BT,
                                                  const float* __restrict__ bias,
                                                  float* __restrict__ C,
                                                  int M, int N, int K)
{
    const int BK = 32, LDW = 40;
    __shared__ __align__(16) __nv_bfloat16 As[2][128*LDW];
    __shared__ __align__(16) __nv_bfloat16 Bs[2][128*LDW];
    int tid = threadIdx.x, lane = tid & 31, wid = tid >> 5;
    int wm = wid & 3, wn = wid >> 2;
    int gid = lane >> 2, tig = lane & 3;
    int row0 = blockIdx.x * 128, col0 = blockIdx.y * 128;
    uint32_t sA = (uint32_t)__cvta_generic_to_shared(&As[0][0]);
    uint32_t sB = (uint32_t)__cvta_generic_to_shared(&Bs[0][0]);
    const uint32_t STG = 128*LDW*2;

    int r0s = (tid*2) >> 2, q0 = ((tid*2) & 3)*8;
    int r1s = (tid*2+1) >> 2, q1 = ((tid*2+1) & 3)*8;

    float c[2][8][4];
    #pragma unroll
    for (int mt=0; mt<2; mt++){
        #pragma unroll
        for (int nt=0; nt<8; nt++){
            #pragma unroll
            for (int q=0; q<4; q++) c[mt][nt][q] = 0.f;
        }
    }

    int nch = K / BK;
    {
        CP_ASYNC16(sA + (uint32_t)(r0s*LDW + q0)*2, A + (size_t)(row0 + r0s)*K + q0);
        CP_ASYNC16(sA + (uint32_t)(r1s*LDW + q1)*2, A + (size_t)(row0 + r1s)*K + q1);
        CP_ASYNC16(sB + (uint32_t)(r0s*LDW + q0)*2, BT + (size_t)(col0 + r0s)*K + q0);
        CP_ASYNC16(sB + (uint32_t)(r1s*LDW + q1)*2, BT + (size_t)(col0 + r1s)*K + q1);
        CP_COMMIT();
    }
    int lq = lane >> 3, lr = lane & 7;

    for (int kc = 0; kc < nch; kc++){
        int cur = kc & 1;
        if (kc + 1 < nch){
            int nxt = (kc+1) & 1;
            int k0 = (kc+1)*BK;
            CP_ASYNC16(sA + nxt*STG + (uint32_t)(r0s*LDW + q0)*2, A + (size_t)(row0 + r0s)*K + k0 + q0);
            CP_ASYNC16(sA + nxt*STG + (uint32_t)(r1s*LDW + q1)*2, A + (size_t)(row0 + r1s)*K + k0 + q1);
            CP_ASYNC16(sB + nxt*STG + (uint32_t)(r0s*LDW + q0)*2, BT + (size_t)(col0 + r0s)*K + k0 + q0);
            CP_ASYNC16(sB + nxt*STG + (uint32_t)(r1s*LDW + q1)*2, BT + (size_t)(col0 + r1s)*K + k0 + q1);
            CP_COMMIT();
            CP_WAIT(1);
        } else {
            CP_WAIT(0);
        }
        __syncthreads();
        uint32_t baseA = sA + cur*STG, baseB = sB + cur*STG;
        #pragma unroll
        for (int kk = 0; kk < BK; kk += 16){
            uint32_t a[2][4], b[8][2];
            #pragma unroll
            for (int mt=0; mt<2; mt++){
                int row = wm*32 + mt*16 + (lq&1)*8 + lr;
                int col = kk + (lq>>1)*8;
                uint32_t addr = baseA + (uint32_t)(row*LDW + col)*2;
                asm volatile("ldmatrix.sync.aligned.m8n8.x4.shared.b16 {%0,%1,%2,%3}, [%4];"
                    : "=r"(a[mt][0]), "=r"(a[mt][1]), "=r"(a[mt][2]), "=r"(a[mt][3]) : "r"(addr));
            }
            #pragma unroll
            for (int p=0; p<4; p++){
                int row = wn*64 + p*16 + (lq&1)*8 + lr;
                int col = kk + (lq>>1)*8;
                uint32_t addr = baseB + (uint32_t)(row*LDW + col)*2;
                asm volatile("ldmatrix.sync.aligned.m8n8.x4.shared.b16 {%0,%1,%2,%3}, [%4];"
                    : "=r"(b[2*p][0]), "=r"(b[2*p+1][0]), "=r"(b[2*p][1]), "=r"(b[2*p+1][1]) : "r"(addr));
            }
            #pragma unroll
            for (int mt=0; mt<2; mt++){
                #pragma unroll
                for (int nt=0; nt<8; nt++)
                    asm("mma.sync.aligned.m16n8k16.row.col.f32.bf16.bf16.f32 "
                        "{%0,%1,%2,%3}, {%4,%5,%6,%7}, {%8,%9}, {%0,%1,%2,%3};"
                        : "+f"(c[mt][nt][0]), "+f"(c[mt][nt][1]),
                          "+f"(c[mt][nt][2]), "+f"(c[mt][nt][3])
                        : "r"(a[mt][0]), "r"(a[mt][1]), "r"(a[mt][2]), "r"(a[mt][3]),
                          "r"(b[nt][0]), "r"(b[nt][1]));
            }
        }
        __syncthreads();
    }
    #pragma unroll
    for (int mt=0; mt<2; mt++){
        int r = row0 + wm*32 + mt*16 + gid;
        #pragma unroll
        for (int nt=0; nt<8; nt++){
            int cc = col0 + wn*64 + nt*8 + tig*2;
            float b0 = bias ? bias[cc] : 0.f;
            float b1 = bias ? bias[cc+1] : 0.f;
            C[(size_t)r*N + cc]       = c[mt][nt][0] + b0;
            C[(size_t)r*N + cc + 1]   = c[mt][nt][1] + b1;
            C[(size_t)(r+8)*N + cc]   = c[mt][nt][2] + b0;
            C[(size_t)(r+8)*N + cc+1] = c[mt][nt][3] + b1;
        }
    }
}

// ---------------- tf32 mma.sync GEMM, fp32 out + bias ----------------
__global__ void tf32gemm_k(const float* __restrict__ A, const float* __restrict__ Bm,
                           const float* __restrict__ bias, float* __restrict__ C,
                           int M, int N, int K)
{
    __shared__ float As[16][132];
    __shared__ float Bs[16][132];
    int tid = threadIdx.x, lane = tid & 31, wid = tid >> 5;
    int wm = wid & 3, wn = wid >> 2;
    int gid = lane >> 2, tig = lane & 3;
    int row0 = blockIdx.x * 128, col0 = blockIdx.y * 128;

    float c[2][8][4];
    #pragma unroll
    for (int mt=0; mt<2; mt++){
        #pragma unroll
        for (int nt=0; nt<8; nt++){
            #pragma unroll
            for (int q=0; q<4; q++) c[mt][nt][q] = 0.f;
        }
    }

    for (int k0 = 0; k0 < K; k0 += 16){
        #pragma unroll
        for (int j = 0; j < 2; j++){
            int s = tid*2 + j;
            int r = s >> 2, kq = (s & 3)*4;
            float4 v = *reinterpret_cast<const float4*>(&A[(size_t)(row0 + r)*K + k0 + kq]);
            As[kq+0][r] = __uint_as_float(f2tf32(v.x));
            As[kq+1][r] = __uint_as_float(f2tf32(v.y));
            As[kq+2][r] = __uint_as_float(f2tf32(v.z));
            As[kq+3][r] = __uint_as_float(f2tf32(v.w));
        }
        #pragma unroll
        for (int j = 0; j < 2; j++){
            int s = tid*2 + j;
            int r = s >> 5, c4 = (s & 31)*4;
            float4 v = *reinterpret_cast<const float4*>(&Bm[(size_t)(k0 + r)*N + col0 + c4]);
            Bs[r][c4+0] = __uint_as_float(f2tf32(v.x));
            Bs[r][c4+1] = __uint_as_float(f2tf32(v.y));
            Bs[r][c4+2] = __uint_as_float(f2tf32(v.z));
            Bs[r][c4+3] = __uint_as_float(f2tf32(v.w));
        }
        __syncthreads();
        #pragma unroll
        for (int kk = 0; kk < 2; kk++){
            int kb = kk*8;
            uint32_t a[2][4], b[8][2];
            #pragma unroll
            for (int mt=0; mt<2; mt++){
                int r = wm*32 + mt*16 + gid;
                a[mt][0] = __float_as_uint(As[kb+tig  ][r  ]);
                a[mt][1] = __float_as_uint(As[kb+tig  ][r+8]);
                a[mt][2] = __float_as_uint(As[kb+tig+4][r  ]);
                a[mt][3] = __float_as_uint(As[kb+tig+4][r+8]);
            }
            #pragma unroll
            for (int nt=0; nt<8; nt++){
                int n = wn*64 + nt*8 + gid;
                b[nt][0] = __float_as_uint(Bs[kb+tig  ][n]);
                b[nt][1] = __float_as_uint(Bs[kb+tig+4][n]);
            }
            #pragma unroll
            for (int mt=0; mt<2; mt++){
                #pragma unroll
                for (int nt=0; nt<8; nt++)
                    asm("mma.sync.aligned.m16n8k8.row.col.f32.tf32.tf32.f32 "
                        "{%0,%1,%2,%3}, {%4,%5,%6,%7}, {%8,%9}, {%0,%1,%2,%3};"
                        : "+f"(c[mt][nt][0]), "+f"(c[mt][nt][1]),
                          "+f"(c[mt][nt][2]), "+f"(c[mt][nt][3])
                        : "r"(a[mt][0]), "r"(a[mt][1]), "r"(a[mt][2]), "r"(a[mt][3]),
                          "r"(b[nt][0]), "r"(b[nt][1]));
            }
        }
        __syncthreads();
    }
    #pragma unroll
    for (int mt=0; mt<2; mt++){
        int r = row0 + wm*32 + mt*16 + gid;
        #pragma unroll
        for (int nt=0; nt<8; nt++){
            int cc = col0 + wn*64 + nt*8 + tig*2;
            float b0 = bias ? bias[cc] : 0.f;
            float b1 = bias ? bias[cc+1] : 0.f;
            C[(size_t)r*N + cc]       = c[mt][nt][0] + b0;
            C[(size_t)r*N + cc + 1]   = c[mt][nt][1] + b1;
            C[(size_t)(r+8)*N + cc]   = c[mt][nt][2] + b0;
            C[(size_t)(r+8)*N + cc+1] = c[mt][nt][3] + b1;
        }
    }
}

// ---------------- tf32 mma.sync GEMM, bf16 output (proj_e) ----------------
__global__ void tf32gemm_bf16o_k(const float* __restrict__ A, const float* __restrict__ Bm,
                                 __nv_bfloat16* __restrict__ Cb, int M, int N, int K)
{
    __shared__ float As[16][132];
    __shared__ float Bs[16][132];
    int tid = threadIdx.x, lane = tid & 31, wid = tid >> 5;
    int wm = wid & 3, wn = wid >> 2;
    int gid = lane >> 2, tig = lane & 3;
    int row0 = blockIdx.x * 128, col0 = blockIdx.y * 128;

    float c[2][8][4];
    #pragma unroll
    for (int mt=0; mt<2; mt++){
        #pragma unroll
        for (int nt=0; nt<8; nt++){
            #pragma unroll
            for (int q=0; q<4; q++) c[mt][nt][q] = 0.f;
        }
    }

    for (int k0 = 0; k0 < K; k0 += 16){
        #pragma unroll
        for (int j = 0; j < 2; j++){
            int s = tid*2 + j;
            int r = s >> 2, kq = (s & 3)*4;
            float4 v = *reinterpret_cast<const float4*>(&A[(size_t)(row0 + r)*K + k0 + kq]);
            As[kq+0][r] = __uint_as_float(f2tf32(v.x));
            As[kq+1][r] = __uint_as_float(f2tf32(v.y));
            As[kq+2][r] = __uint_as_float(f2tf32(v.z));
            As[kq+3][r] = __uint_as_float(f2tf32(v.w));
        }
        #pragma unroll
        for (int j = 0; j < 2; j++){
            int s = tid*2 + j;
            int r = s >> 5, c4 = (s & 31)*4;
            float4 v = *reinterpret_cast<const float4*>(&Bm[(size_t)(k0 + r)*N + col0 + c4]);
            Bs[r][c4+0] = __uint_as_float(f2tf32(v.x));
            Bs[r][c4+1] = __uint_as_float(f2tf32(v.y));
            Bs[r][c4+2] = __uint_as_float(f2tf32(v.z));
            Bs[r][c4+3] = __uint_as_float(f2tf32(v.w));
        }
        __syncthreads();
        #pragma unroll
        for (int kk = 0; kk < 2; kk++){
            int kb = kk*8;
            uint32_t a[2][4], b[8][2];
            #pragma unroll
            for (int mt=0; mt<2; mt++){
                int r = wm*32 + mt*16 + gid;
                a[mt][0] = __float_as_uint(As[kb+tig  ][r  ]);
                a[mt][1] = __float_as_uint(As[kb+tig  ][r+8]);
                a[mt][2] = __float_as_uint(As[kb+tig+4][r  ]);
                a[mt][3] = __float_as_uint(As[kb+tig+4][r+8]);
            }
            #pragma unroll
            for (int nt=0; nt<8; nt++){
                int n = wn*64 + nt*8 + gid;
                b[nt][0] = __float_as_uint(Bs[kb+tig  ][n]);
                b[nt][1] = __float_as_uint(Bs[kb+tig+4][n]);
            }
            #pragma unroll
            for (int mt=0; mt<2; mt++){
                #pragma unroll
                for (int nt=0; nt<8; nt++)
                    asm("mma.sync.aligned.m16n8k8.row.col.f32.tf32.tf32.f32 "
                        "{%0,%1,%2,%3}, {%4,%5,%6,%7}, {%8,%9}, {%0,%1,%2,%3};"
                        : "+f"(c[mt][nt][0]), "+f"(c[mt][nt][1]),
                          "+f"(c[mt][nt][2]), "+f"(c[mt][nt][3])
                        : "r"(a[mt][0]), "r"(a[mt][1]), "r"(a[mt][2]), "r"(a[mt][3]),
                          "r"(b[nt][0]), "r"(b[nt][1]));
            }
        }
        __syncthreads();
    }
    #pragma unroll
    for (int mt=0; mt<2; mt++){
        int r = row0 + wm*32 + mt*16 + gid;
        #pragma unroll
        for (int nt=0; nt<8; nt++){
            int cc = col0 + wn*64 + nt*8 + tig*2;
            Cb[(size_t)r*N + cc]       = __float2bfloat16(c[mt][nt][0]);
            Cb[(size_t)r*N + cc + 1]   = __float2bfloat16(c[mt][nt][1]);
            Cb[(size_t)(r+8)*N + cc]   = __float2bfloat16(c[mt][nt][2]);
            Cb[(size_t)(r+8)*N + cc+1] = __float2bfloat16(c[mt][nt][3]);
        }
    }
}

// tiled SGEMM, packed f32x2 FMA (small transition GEMMs)
template<int ACT>
__global__ void sgemm_k(const float* __restrict__ A, const float* __restrict__ Bm,
                        const float* __restrict__ bias, float* __restrict__ C,
                        int M, int N, int K)
{
    const int BM=64, BN=128, BK=16, TM=4, TN=8, THREADS=256;
    __shared__ float As[BM][BK+1];
    __shared__ __align__(16) float Bs[BK][BN];
    int tid = threadIdx.x;
    int tx = tid % (BN/TN), ty = tid / (BN/TN);
    int row0 = blockIdx.y*BM, col0 = blockIdx.x*BN;
    unsigned long long acc2[TM][TN/2];
    #pragma unroll
    for (int m=0;m<TM;m++){
        #pragma unroll
        for (int i=0;i<TN/2;i++) acc2[m][i]=0ull;
    }
    for (int k0 = 0; k0 < K; k0 += BK){
        for (int l = tid; l < BM*BK; l += THREADS){
            int r=l/BK, c=l%BK;
            As[r][c] = A[(size_t)(row0+r)*K + k0 + c];
        }
        for (int l = tid; l < BK*BN; l += THREADS){
            int r=l/BN, c=l%BN, gc=col0+c;
            Bs[r][c] = (gc<N) ? Bm[(size_t)(k0+r)*N + gc] : 0.f;
        }
        __syncthreads();
        #pragma unroll
        for (int kk=0; kk<BK; kk++){
            unsigned long long b2[TN/2];
            #pragma unroll
            for (int i=0;i<TN/2;i++)
                b2[i] = *reinterpret_cast<const unsigned long long*>(&Bs[kk][tx*TN+2*i]);
            #pragma unroll
            for (int m=0;m<TM;m++){
                float av = As[ty*TM+m][kk];
                unsigned long long a2;
                asm("mov.b64 %0, {%1, %1};" : "=l"(a2) : "r"(__float_as_uint(av)));
                #pragma unroll
                for (int i=0;i<TN/2;i++)
                    asm("fma.rn.f32x2 %0, %1, %2, %0;" : "+l"(acc2[m][i]) : "l"(a2), "l"(b2[i]));
            }
        }
        __syncthreads();
    }
    #pragma unroll
    for (int m=0;m<TM;m++){
        int gr = row0 + ty*TM + m;
        #pragma unroll
        for (int i=0;i<TN/2;i++){
            unsigned lo,hi;
            asm("mov.b64 {%0, %1}, %2;" : "=r"(lo), "=r"(hi) : "l"(acc2[m][i]));
            int gc0 = col0 + tx*TN + 2*i;
            if (gc0 < N){
                float v = __uint_as_float(lo);
                if (bias) v += bias[gc0];
                if (ACT) v = tanhf(v);
                C[(size_t)gr*N + gc0] = v;
            }
            if (gc0+1 < N){
                float v = __uint_as_float(hi);
                if (bias) v += bias[gc0+1];
                if (ACT) v = tanhf(v);
                C[(size_t)gr*N + gc0+1] = v;
            }
        }
    }
}

// ---------------- fused LSTM step: recurrent GEMM + gates + state update ----------------
// grid (16 chunks, 2 dirs), 512 threads. Gate-interleaved layout c = h*4+g.
__global__ void __launch_bounds__(512) k_lstm_step(const int* __restrict__ lengths, int t){
    int ch = blockIdx.x, dir = blockIdx.y;
    __shared__ __align__(16) float hsT[H_*16];       // 32 KB [k][b]
    __shared__ float red[4*128*16];                  // 32 KB [kq][c][b]
    int tid = threadIdx.x;
    const float* hprev = d_hstate + dir*(B_*H_);
    for (int i = tid; i < H_*16; i += 512){
        int k = i >> 4, b = i & 15;
        hsT[i] = hprev[b*H_ + k];
    }
    __syncthreads();

    int c = tid & 127, kq = tid >> 7;
    const float* wp = d_whP + (size_t)dir*H_*G4_ + (size_t)(kq*128)*G4_ + ch*128 + c;
    unsigned long long acc2[8] = {0,0,0,0,0,0,0,0};
    const unsigned long long* hbase = reinterpret_cast<const unsigned long long*>(&hsT[(kq*128)*16]);
    #pragma unroll 4
    for (int k = 0; k < 128; k++){
        float w = wp[(size_t)k*G4_];
        unsigned long long w2;
        asm("mov.b64 %0, {%1, %1};" : "=l"(w2) : "r"(__float_as_uint(w)));
        const unsigned long long* hv = hbase + k*8;
        #pragma unroll
        for (int j=0;j<8;j++)
            asm("fma.rn.f32x2 %0, %1, %2, %0;" : "+l"(acc2[j]) : "l"(hv[j]), "l"(w2));
    }
    float* rr = &red[(kq*128 + c)*16];
    #pragma unroll
    for (int j=0;j<8;j++){
        unsigned lo,hi;
        asm("mov.b64 {%0, %1}, %2;" : "=r"(lo), "=r"(hi) : "l"(acc2[j]));
        rr[2*j]   = __uint_as_float(lo);
        rr[2*j+1] = __uint_as_float(hi);
    }
    __syncthreads();

    // reduce split-K + add gpre (permuted) -> gates into red[0] region
    const float* gpre = (dir ? d_gpre_bw : d_gpre_fw);
    for (int i = tid; i < 2048; i += 512){
        int cc = i >> 4, b = i & 15;
        float s = red[(0*128+cc)*16+b] + red[(1*128+cc)*16+b]
                + red[(2*128+cc)*16+b] + red[(3*128+cc)*16+b];
        s += gpre[(size_t)(b*T_ + t)*G4_ + ch*128 + cc];
        red[(0*128+cc)*16+b] = s;
    }
    __syncthreads();

    // combine: 512 threads = 32 hidden units x 16 batches
    int hl = tid >> 4, b = tid & 15;
    float gi = red[((hl*4+0))*16 + b];
    float gj = red[((hl*4+1))*16 + b];
    float gf = red[((hl*4+2))*16 + b];
    float go = red[((hl*4+3))*16 + b];
    int hg = ch*32 + hl;
    int idx = (dir*B_ + b)*H_ + hg;
    float cs = d_cstate[idx], hp = d_hstate[idx];
    float cn = sigmf(gf + 1.f)*cs + sigmf(gi)*tanhf(gj);
    float hn = sigmf(go)*tanhf(cn);
    int len = lengths[b];
    bool m = (t < len);
    d_cstate[idx] = m ? cn : cs;
    d_hstate[idx] = m ? hn : hp;
    float ho = m ? hn : 0.f;
    if (dir == 0) d_hcat[(size_t)(b*T_ + t)*(2*H_) + hg] = ho;
    else { int p = m ? (len-1-t) : t; d_hcat[(size_t)(b*T_ + p)*(2*H_) + H_ + hg] = ho; }
}

// single-pass online softmax row reduce over 32000 logits
__global__ void k_rowreduce(){
    int row = blockIdx.x, tid = threadIdx.x;
    const float4* p = reinterpret_cast<const float4*>(d_logits + (size_t)row*VS_);
    float m = -1e30f, s = 0.f;
    for (int v = tid; v < VS_/4; v += 256){
        float4 x = p[v];
        #pragma unroll
        for (int q = 0; q < 4; q++){
            float xv = (q==0)?x.x:(q==1)?x.y:(q==2)?x.z:x.w;
            if (xv > m){ s = s*expf(m - xv) + 1.f; m = xv; }
            else        s += expf(xv - m);
        }
    }
    __shared__ float sm[256], ss[256];
    sm[tid] = m; ss[tid] = s; __syncthreads();
    for (int st = 128; st > 0; st >>= 1){
        if (tid < st){
            float m1 = sm[tid], m2 = sm[tid+st];
            float mm = fmaxf(m1, m2);
            ss[tid] = ss[tid]*expf(m1-mm) + ss[tid+st]*expf(m2-mm);
            sm[tid] = mm;
        }
        __syncthreads();
    }
    if (tid == 0){ d_rowmax[row] = sm[0]; d_rowsum[row] = ss[0]; }
}

__global__ void k_nulllogits(const float* __restrict__ Wv, const float* __restrict__ bv){
    __shared__ float ns[H_];
    int tid = threadIdx.x;
    for (int k=tid; k<H_; k+=256) ns[k] = d_nullstate[k];
    __syncthreads();
    int v = blockIdx.x*256 + tid;
    if (v < VS_){
        float a = bv[v];
        #pragma unroll 4
        for (int k=0;k<H_;k++) a = fmaf(ns[k], Wv[(size_t)k*VS_+v], a);
        d_nulllog[v] = a;
    }
}

__global__ void k_nullreduce(){
    __shared__ float sm[1024];
    int tid = threadIdx.x;
    float m = -1e30f;
    for (int v=tid; v<VS_; v+=1024) m = fmaxf(m, d_nulllog[v]);
    sm[tid]=m; __syncthreads();
    for (int s=512;s>0;s>>=1){ if(tid<s) sm[tid]=fmaxf(sm[tid],sm[tid+s]); __syncthreads(); }
    float mx = sm[0]; __syncthreads();
    float su = 0.f;
    for (int v=tid; v<VS_; v+=1024) su += expf(d_nulllog[v]-mx);
    sm[tid]=su; __syncthreads();
    for (int s=512;s>0;s>>=1){ if(tid<s) sm[tid]+=sm[tid+s]; __syncthreads(); }
    if (tid==0){ d_nullred[0]=mx; d_nullred[1]=sm[0]; }
}

__global__ void k_emission(const int* __restrict__ sources, float* __restrict__ out){
    int bt = blockIdx.x, b = bt>>6, t = bt&63, s = threadIdx.x;   // 64
    int col = sources[b*S_+s];
    float l = d_logits[(size_t)bt*VS_ + col];
    out[(size_t)b*(2*T_*S_) + t*S_ + s] = expf(l - d_rowmax[bt]) / d_rowsum[bt];
    out[(size_t)b*(2*T_*S_) + (T_+t)*S_ + s] = expf(d_nulllog[col]-d_nullred[0]) / d_nullred[1];
}

__global__ void k_jsoftmax(){
    int row = blockIdx.x, tid = threadIdx.x;
    float* p = d_jl + (size_t)row*J_;
    __shared__ float sm[256];
    float m = -1e30f;
    for (int j=tid; j<J_; j+=256) m = fmaxf(m, p[j]);
    sm[tid]=m; __syncthreads();
    for (int s=128;s>0;s>>=1){ if(tid<s) sm[tid]=fmaxf(sm[tid],sm[tid+s]); __syncthreads(); }
    float mx = sm[0]; __syncthreads();
    float su = 0.f;
    for (int j=tid; j<J_; j+=256) su += expf(p[j]-mx);
    sm[tid]=su; __syncthreads();
    for (int s=128;s>0;s>>=1){ if(tid<s) sm[tid]+=sm[tid+s]; __syncthreads(); }
    float inv = 1.f/sm[0]; __syncthreads();
    for (int j=tid; j<J_; j+=256) p[j] = expf(p[j]-mx)*inv;
}

__global__ void k_p0(const float* __restrict__ Wp0, const float* __restrict__ bp0){
    int gw = (blockIdx.x*blockDim.x + threadIdx.x) >> 5;
    int lane = threadIdx.x & 31;
    if (gw >= BT_) return;
    float a = 0.f;
    for (int k=lane; k<H_; k+=32) a = fmaf(d_tt[(size_t)gw*H_+k], Wp0[k], a);
    #pragma unroll
    for (int o=16;o>0;o>>=1) a += __shfl_xor_sync(0xffffffffu, a, o);
    if (lane==0) d_p0v[gw] = sigmf(a + bp0[0]);
}

__global__ void k_transition(float* __restrict__ out){
    int b = blockIdx.y;
    int idx = blockIdx.x*256 + threadIdx.x;
    if (idx >= T_*2*T_) return;
    int i = idx / (2*T_), c = idx % (2*T_);
    float tv, lv;
    if (c < T_){
        float jw = d_jl[(size_t)(b*T_+i)*J_ + (MM_ + c - i)];
        tv = jw; lv = logf(jw);
    } else {
        int j = c - T_;
        float p = d_p0v[b*T_+i];
        tv = (i==j) ? p : 0.f;
        lv = (i==j) ? logf(p) : 0.f;
    }
    float* tr  = out + (size_t)B_*2*T_*S_ + (size_t)b*(2*T_*2*T_);
    float* trl = tr + (size_t)B_*2*T_*2*T_;
    tr [i*2*T_ + c] = tv;  tr [(T_+i)*2*T_ + c] = tv;
    trl[i*2*T_ + c] = lv;  trl[(T_+i)*2*T_ + c] = lv;
}

extern "C" void kernel_launch(void* const* d_in, const int* in_sizes, int n_in,
                              void* d_out, int out_size) {
    const int*   sources = (const int*)  d_in[0];
    const int*   targets = (const int*)  d_in[1];
    const int*   tnull   = (const int*)  d_in[2];
    const int*   lengths = (const int*)  d_in[3];
    const float* emb     = (const float*)d_in[4];
    const float* nnW     = (const float*)d_in[5];
    const float* nnb     = (const float*)d_in[6];
    const float* Wx_fw   = (const float*)d_in[7];
    const float* Wh_fw   = (const float*)d_in[8];
    const float* b_fw    = (const float*)d_in[9];
    const float* Wx_bw   = (const float*)d_in[10];
    const float* Wh_bw   = (const float*)d_in[11];
    const float* b_bw    = (const float*)d_in[12];
    const float* Wproj_e = (const float*)d_in[13];
    const float* Wv      = (const float*)d_in[14];
    const float* bv      = (const float*)d_in[15];
    const float* Wproj_t = (const float*)d_in[16];
    const float* Wj      = (const float*)d_in[17];
    const float* bj      = (const float*)d_in[18];
    const float* Wp0     = (const float*)d_in[19];
    const float* bp0     = (const float*)d_in[20];
    float* out = (float*)d_out;

    float *gfw, *gbw, *xp, *xrp, *hc, *lg, *tmp, *ttp, *jl, *wxP, *bP;
    __nv_bfloat16 *tsb, *wvT;
    cudaGetSymbolAddress((void**)&gfw, d_gpre_fw);
    cudaGetSymbolAddress((void**)&gbw, d_gpre_bw);
    cudaGetSymbolAddress((void**)&xp,  d_x);
    cudaGetSymbolAddress((void**)&xrp, d_xrev);
    cudaGetSymbolAddress((void**)&hc,  d_hcat);
    cudaGetSymbolAddress((void**)&lg,  d_logits);
    cudaGetSymbolAddress((void**)&tmp, d_tmpt);
    cudaGetSymbolAddress((void**)&ttp, d_tt);
    cudaGetSymbolAddress((void**)&jl,  d_jl);
    cudaGetSymbolAddress((void**)&tsb, d_tsb);
    cudaGetSymbolAddress((void**)&wvT, d_wvT);
    cudaGetSymbolAddress((void**)&wxP, d_wxP);
    cudaGetSymbolAddress((void**)&bP,  d_bP);

    k_init<<<64,256>>>();
    k_embed<<<BT_,256>>>(targets, lengths, emb);
    k_nullstate<<<1,512>>>(tnull, emb, nnW, nnb);
    k_permw<<<512,256>>>(Wx_fw, Wx_bw, b_fw, b_bw, Wh_fw, Wh_bw);
    k_cvt_wvT<<<dim3(1000,16),dim3(32,8)>>>(Wv);

    // input projections (tf32) into permuted gate layout
    tf32gemm_k<<<dim3(8,16),256>>>(xp,  wxP,           bP,       gfw, BT_, G4_, E_);
    tf32gemm_k<<<dim3(8,16),256>>>(xrp, wxP + E_*G4_,  bP + G4_, gbw, BT_, G4_, E_);

    for (int t = 0; t < T_; t++)
        k_lstm_step<<<dim3(16,2),512>>>(lengths, t);

    // emission path: proj_e (tf32 -> bf16 out), logits (bf16 mma.sync)
    tf32gemm_bf16o_k<<<dim3(8,4),256>>>(hc, Wproj_e, tsb, BT_, H_, 2*H_);
    bf16gemm_k<<<dim3(8,250),256>>>(tsb, wvT, bv, lg, BT_, VS_, H_);
    k_rowreduce<<<BT_,256>>>();
    k_nulllogits<<<125,256>>>(Wv, bv);
    k_nullreduce<<<1,1024>>>();
    k_emission<<<BT_,64>>>(sources, out);

    // transition path (fp32, small)
    sgemm_k<0><<<dim3(2,16),256>>>(hc, Wproj_t, nullptr, tmp, BT_, E_, 2*H_);
    sgemm_k<1><<<dim3(4,16),256>>>(tmp, nnW, nnb, ttp, BT_, H_, E_);
    sgemm_k<0><<<dim3(2,16),256>>>(ttp, Wj, bj, jl, BT_, J_, H_);
    k_jsoftmax<<<BT_,256>>>();
    k_p0<<<128,256>>>(Wp0, bp0);
    k_transition<<<dim3(32,16),256>>>(out);
}

// round 12
// speedup vs baseline: 1.4718x; 1.4718x over previous
#include <cuda_runtime.h>
#include <cuda_bf16.h>
#include <cstdint>

#define B_  16
#define S_  64
#define T_  64
#define E_  256
#define H_  512
#define VS_ 32000
#define MM_ 100
#define J_  201
#define BT_ (B_*T_)
#define G4_ (4*H_)

__device__ float d_x[BT_*E_];
__device__ float d_xrev[BT_*E_];
__device__ float d_gpre_fw[BT_*G4_];    // standard layout g*H+h
__device__ float d_gpre_bw[BT_*G4_];
__device__ float d_hstate[2*B_*H_];
__device__ float d_cstate[2*B_*H_];
__device__ float d_hcat[BT_*2*H_];
__device__ float d_logits[(size_t)BT_*VS_];
__device__ float d_rowmax[BT_];
__device__ float d_rowsum[BT_];
__device__ float d_nullstate[H_];
__device__ float d_nulllog[VS_];
__device__ float d_nullred[2];
__device__ float d_tmpt[BT_*E_];
__device__ float d_tt[BT_*H_];
__device__ float d_jl[BT_*J_];
__device__ float d_p0v[BT_];
__device__ __nv_bfloat16 d_tsb[BT_*H_];
__device__ __nv_bfloat16 d_wvT[(size_t)VS_*H_];
__device__ float d_whP[2*H_*G4_];       // [dir][k][c] permuted: c = h*4+g

__device__ __forceinline__ float sigmf(float x){ return 1.f/(1.f+expf(-x)); }
__device__ __forceinline__ uint32_t f2tf32(float v){
    uint32_t r; asm("cvt.rna.tf32.f32 %0, %1;" : "=r"(r) : "f"(v)); return r;
}

__global__ void k_init(){
    int i = blockIdx.x*blockDim.x + threadIdx.x;
    if (i < 2*B_*H_){ d_hstate[i]=0.f; d_cstate[i]=0.f; }
}

__global__ void k_embed(const int* __restrict__ targets, const int* __restrict__ lengths,
                        const float* __restrict__ emb){
    int bt = blockIdx.x, b = bt/T_, t = bt%T_;
    int len = lengths[b];
    int rt = (t < len) ? (len-1-t) : t;
    int r0 = targets[bt], r1 = targets[b*T_+rt];
    for (int e = threadIdx.x; e < E_; e += blockDim.x){
        d_x[bt*E_+e]    = emb[(size_t)r0*E_+e];
        d_xrev[bt*E_+e] = emb[(size_t)r1*E_+e];
    }
}

__global__ void k_nullstate(const int* __restrict__ tnull, const float* __restrict__ emb,
                            const float* __restrict__ nnW, const float* __restrict__ nnb){
    __shared__ float xe[E_];
    int tid = threadIdx.x;          // 512
    int r = tnull[0];
    for (int e = tid; e < E_; e += blockDim.x) xe[e] = emb[(size_t)r*E_+e];
    __syncthreads();
    float a = nnb[tid];
    #pragma unroll 4
    for (int e = 0; e < E_; e++) a = fmaf(xe[e], nnW[e*H_+tid], a);
    d_nullstate[tid] = tanhf(a);
}

// permute Wh to gate-interleaved layout: c = h*4+g  <-  g*H+h
__global__ void k_permwh(const float* __restrict__ Whf, const float* __restrict__ Whb){
    int stride = gridDim.x*blockDim.x;
    for (int i = blockIdx.x*blockDim.x + threadIdx.x; i < 2*H_*G4_; i += stride){
        int dir = i / (H_*G4_); int r = (i >> 11) & (H_-1); int c = i & (G4_-1);
        int g = c & 3, h = c >> 2;
        d_whP[i] = (dir ? Whb : Whf)[(size_t)r*G4_ + g*H_ + h];
    }
}

// transpose+convert Wv [H,VS] fp32 -> d_wvT [VS,H] bf16
__global__ void k_cvt_wvT(const float* __restrict__ Wv){
    __shared__ float tile[32][33];
    int nb = blockIdx.x, kb = blockIdx.y;
    int tx = threadIdx.x, ty = threadIdx.y;   // 32 x 8
    #pragma unroll
    for (int i = 0; i < 32; i += 8)
        tile[ty+i][tx] = Wv[(size_t)(kb*32+ty+i)*VS_ + nb*32+tx];
    __syncthreads();
    #pragma unroll
    for (int i = 0; i < 32; i += 8)
        d_wvT[(size_t)(nb*32+ty+i)*H_ + kb*32+tx] = __float2bfloat16(tile[tx][ty+i]);
}

#define CP_ASYNC16(dst, src) \
    asm volatile("cp.async.cg.shared.global [%0], [%1], 16;\n" :: "r"(dst), "l"(src))
#define CP_COMMIT() asm volatile("cp.async.commit_group;\n" ::: "memory")
#define CP_WAIT(n)  asm volatile("cp.async.wait_group %0;\n" :: "n"(n) : "memory")

// ---------------- bf16 mma.sync GEMM (R10, unchanged) ----------------
__global__ void __launch_bounds__(256) bf16gemm_k(const __nv_bfloat16* __restrict__ A,
                                                  const __nv_bfloat16* __restrict__ BT,
                                                  const float* __restrict__ bias,
                                                  float* __restrict__ C,
                                                  int M, int N, int K)
{
    const int BK = 32, LDW = 40;
    __shared__ __align__(16) __nv_bfloat16 As[2][128*LDW];
    __shared__ __align__(16) __nv_bfloat16 Bs[2][128*LDW];
    int tid = threadIdx.x, lane = tid & 31, wid = tid >> 5;
    int wm = wid & 3, wn = wid >> 2;
    int gid = lane >> 2, tig = lane & 3;
    int row0 = blockIdx.x * 128, col0 = blockIdx.y * 128;
    uint32_t sA = (uint32_t)__cvta_generic_to_shared(&As[0][0]);
    uint32_t sB = (uint32_t)__cvta_generic_to_shared(&Bs[0][0]);
    const uint32_t STG = 128*LDW*2;

    int r0s = (tid*2) >> 2, q0 = ((tid*2) & 3)*8;
    int r1s = (tid*2+1) >> 2, q1 = ((tid*2+1) & 3)*8;

    float c[2][8][4];
    #pragma unroll
    for (int mt=0; mt<2; mt++){
        #pragma unroll
        for (int nt=0; nt<8; nt++){
            #pragma unroll
            for (int q=0; q<4; q++) c[mt][nt][q] = 0.f;
        }
    }

    int nch = K / BK;
    {
        CP_ASYNC16(sA + (uint32_t)(r0s*LDW + q0)*2, A + (size_t)(row0 + r0s)*K + q0);
        CP_ASYNC16(sA + (uint32_t)(r1s*LDW + q1)*2, A + (size_t)(row0 + r1s)*K + q1);
        CP_ASYNC16(sB + (uint32_t)(r0s*LDW + q0)*2, BT + (size_t)(col0 + r0s)*K + q0);
        CP_ASYNC16(sB + (uint32_t)(r1s*LDW + q1)*2, BT + (size_t)(col0 + r1s)*K + q1);
        CP_COMMIT();
    }
    int lq = lane >> 3, lr = lane & 7;

    for (int kc = 0; kc < nch; kc++){
        int cur = kc & 1;
        if (kc + 1 < nch){
            int nxt = (kc+1) & 1;
            int k0 = (kc+1)*BK;
            CP_ASYNC16(sA + nxt*STG + (uint32_t)(r0s*LDW + q0)*2, A + (size_t)(row0 + r0s)*K + k0 + q0);
            CP_ASYNC16(sA + nxt*STG + (uint32_t)(r1s*LDW + q1)*2, A + (size_t)(row0 + r1s)*K + k0 + q1);
            CP_ASYNC16(sB + nxt*STG + (uint32_t)(r0s*LDW + q0)*2, BT + (size_t)(col0 + r0s)*K + k0 + q0);
            CP_ASYNC16(sB + nxt*STG + (uint32_t)(r1s*LDW + q1)*2, BT + (size_t)(col0 + r1s)*K + k0 + q1);
            CP_COMMIT();
            CP_WAIT(1);
        } else {
            CP_WAIT(0);
        }
        __syncthreads();
        uint32_t baseA = sA + cur*STG, baseB = sB + cur*STG;
        #pragma unroll
        for (int kk = 0; kk < BK; kk += 16){
            uint32_t a[2][4], b[8][2];
            #pragma unroll
            for (int mt=0; mt<2; mt++){
                int row = wm*32 + mt*16 + (lq&1)*8 + lr;
                int col = kk + (lq>>1)*8;
                uint32_t addr = baseA + (uint32_t)(row*LDW + col)*2;
                asm volatile("ldmatrix.sync.aligned.m8n8.x4.shared.b16 {%0,%1,%2,%3}, [%4];"
                    : "=r"(a[mt][0]), "=r"(a[mt][1]), "=r"(a[mt][2]), "=r"(a[mt][3]) : "r"(addr));
            }
            #pragma unroll
            for (int p=0; p<4; p++){
                int row = wn*64 + p*16 + (lq&1)*8 + lr;
                int col = kk + (lq>>1)*8;
                uint32_t addr = baseB + (uint32_t)(row*LDW + col)*2;
                asm volatile("ldmatrix.sync.aligned.m8n8.x4.shared.b16 {%0,%1,%2,%3}, [%4];"
                    : "=r"(b[2*p][0]), "=r"(b[2*p+1][0]), "=r"(b[2*p][1]), "=r"(b[2*p+1][1]) : "r"(addr));
            }
            #pragma unroll
            for (int mt=0; mt<2; mt++){
                #pragma unroll
                for (int nt=0; nt<8; nt++)
                    asm("mma.sync.aligned.m16n8k16.row.col.f32.bf16.bf16.f32 "
                        "{%0,%1,%2,%3}, {%4,%5,%6,%7}, {%8,%9}, {%0,%1,%2,%3};"
                        : "+f"(c[mt][nt][0]), "+f"(c[mt][nt][1]),
                          "+f"(c[mt][nt][2]), "+f"(c[mt][nt][3])
                        : "r"(a[mt][0]), "r"(a[mt][1]), "r"(a[mt][2]), "r"(a[mt][3]),
                          "r"(b[nt][0]), "r"(b[nt][1]));
            }
        }
        __syncthreads();
    }
    #pragma unroll
    for (int mt=0; mt<2; mt++){
        int r = row0 + wm*32 + mt*16 + gid;
        #pragma unroll
        for (int nt=0; nt<8; nt++){
            int cc = col0 + wn*64 + nt*8 + tig*2;
            float b0 = bias ? bias[cc] : 0.f;
            float b1 = bias ? bias[cc+1] : 0.f;
            C[(size_t)r*N + cc]       = c[mt][nt][0] + b0;
            C[(size_t)r*N + cc + 1]   = c[mt][nt][1] + b1;
            C[(size_t)(r+8)*N + cc]   = c[mt][nt][2] + b0;
            C[(size_t)(r+8)*N + cc+1] = c[mt][nt][3] + b1;
        }
    }
}

// ---------------- tf32 mma.sync GEMM, fp32 out + bias ----------------
__global__ void tf32gemm_k(const float* __restrict__ A, const float* __restrict__ Bm,
                           const float* __restrict__ bias, float* __restrict__ C,
                           int M, int N, int K)
{
    __shared__ float As[16][132];
    __shared__ float Bs[16][132];
    int tid = threadIdx.x, lane = tid & 31, wid = tid >> 5;
    int wm = wid & 3, wn = wid >> 2;
    int gid = lane >> 2, tig = lane & 3;
    int row0 = blockIdx.x * 128, col0 = blockIdx.y * 128;

    float c[2][8][4];
    #pragma unroll
    for (int mt=0; mt<2; mt++){
        #pragma unroll
        for (int nt=0; nt<8; nt++){
            #pragma unroll
            for (int q=0; q<4; q++) c[mt][nt][q] = 0.f;
        }
    }

    for (int k0 = 0; k0 < K; k0 += 16){
        #pragma unroll
        for (int j = 0; j < 2; j++){
            int s = tid*2 + j;
            int r = s >> 2, kq = (s & 3)*4;
            float4 v = *reinterpret_cast<const float4*>(&A[(size_t)(row0 + r)*K + k0 + kq]);
            As[kq+0][r] = __uint_as_float(f2tf32(v.x));
            As[kq+1][r] = __uint_as_float(f2tf32(v.y));
            As[kq+2][r] = __uint_as_float(f2tf32(v.z));
            As[kq+3][r] = __uint_as_float(f2tf32(v.w));
        }
        #pragma unroll
        for (int j = 0; j < 2; j++){
            int s = tid*2 + j;
            int r = s >> 5, c4 = (s & 31)*4;
            float4 v = *reinterpret_cast<const float4*>(&Bm[(size_t)(k0 + r)*N + col0 + c4]);
            Bs[r][c4+0] = __uint_as_float(f2tf32(v.x));
            Bs[r][c4+1] = __uint_as_float(f2tf32(v.y));
            Bs[r][c4+2] = __uint_as_float(f2tf32(v.z));
            Bs[r][c4+3] = __uint_as_float(f2tf32(v.w));
        }
        __syncthreads();
        #pragma unroll
        for (int kk = 0; kk < 2; kk++){
            int kb = kk*8;
            uint32_t a[2][4], b[8][2];
            #pragma unroll
            for (int mt=0; mt<2; mt++){
                int r = wm*32 + mt*16 + gid;
                a[mt][0] = __float_as_uint(As[kb+tig  ][r  ]);
                a[mt][1] = __float_as_uint(As[kb+tig  ][r+8]);
                a[mt][2] = __float_as_uint(As[kb+tig+4][r  ]);
                a[mt][3] = __float_as_uint(As[kb+tig+4][r+8]);
            }
            #pragma unroll
            for (int nt=0; nt<8; nt++){
                int n = wn*64 + nt*8 + gid;
                b[nt][0] = __float_as_uint(Bs[kb+tig  ][n]);
                b[nt][1] = __float_as_uint(Bs[kb+tig+4][n]);
            }
            #pragma unroll
            for (int mt=0; mt<2; mt++){
                #pragma unroll
                for (int nt=0; nt<8; nt++)
                    asm("mma.sync.aligned.m16n8k8.row.col.f32.tf32.tf32.f32 "
                        "{%0,%1,%2,%3}, {%4,%5,%6,%7}, {%8,%9}, {%0,%1,%2,%3};"
                        : "+f"(c[mt][nt][0]), "+f"(c[mt][nt][1]),
                          "+f"(c[mt][nt][2]), "+f"(c[mt][nt][3])
                        : "r"(a[mt][0]), "r"(a[mt][1]), "r"(a[mt][2]), "r"(a[mt][3]),
                          "r"(b[nt][0]), "r"(b[nt][1]));
            }
        }
        __syncthreads();
    }
    #pragma unroll
    for (int mt=0; mt<2; mt++){
        int r = row0 + wm*32 + mt*16 + gid;
        #pragma unroll
        for (int nt=0; nt<8; nt++){
            int cc = col0 + wn*64 + nt*8 + tig*2;
            float b0 = bias ? bias[cc] : 0.f;
            float b1 = bias ? bias[cc+1] : 0.f;
            C[(size_t)r*N + cc]       = c[mt][nt][0] + b0;
            C[(size_t)r*N + cc + 1]   = c[mt][nt][1] + b1;
            C[(size_t)(r+8)*N + cc]   = c[mt][nt][2] + b0;
            C[(size_t)(r+8)*N + cc+1] = c[mt][nt][3] + b1;
        }
    }
}

// ---------------- tf32 mma.sync GEMM, bf16 output (proj_e) ----------------
__global__ void tf32gemm_bf16o_k(const float* __restrict__ A, const float* __restrict__ Bm,
                                 __nv_bfloat16* __restrict__ Cb, int M, int N, int K)
{
    __shared__ float As[16][132];
    __shared__ float Bs[16][132];
    int tid = threadIdx.x, lane = tid & 31, wid = tid >> 5;
    int wm = wid & 3, wn = wid >> 2;
    int gid = lane >> 2, tig = lane & 3;
    int row0 = blockIdx.x * 128, col0 = blockIdx.y * 128;

    float c[2][8][4];
    #pragma unroll
    for (int mt=0; mt<2; mt++){
        #pragma unroll
        for (int nt=0; nt<8; nt++){
            #pragma unroll
            for (int q=0; q<4; q++) c[mt][nt][q] = 0.f;
        }
    }

    for (int k0 = 0; k0 < K; k0 += 16){
        #pragma unroll
        for (int j = 0; j < 2; j++){
            int s = tid*2 + j;
            int r = s >> 2, kq = (s & 3)*4;
            float4 v = *reinterpret_cast<const float4*>(&A[(size_t)(row0 + r)*K + k0 + kq]);
            As[kq+0][r] = __uint_as_float(f2tf32(v.x));
            As[kq+1][r] = __uint_as_float(f2tf32(v.y));
            As[kq+2][r] = __uint_as_float(f2tf32(v.z));
            As[kq+3][r] = __uint_as_float(f2tf32(v.w));
        }
        #pragma unroll
        for (int j = 0; j < 2; j++){
            int s = tid*2 + j;
            int r = s >> 5, c4 = (s & 31)*4;
            float4 v = *reinterpret_cast<const float4*>(&Bm[(size_t)(k0 + r)*N + col0 + c4]);
            Bs[r][c4+0] = __uint_as_float(f2tf32(v.x));
            Bs[r][c4+1] = __uint_as_float(f2tf32(v.y));
            Bs[r][c4+2] = __uint_as_float(f2tf32(v.z));
            Bs[r][c4+3] = __uint_as_float(f2tf32(v.w));
        }
        __syncthreads();
        #pragma unroll
        for (int kk = 0; kk < 2; kk++){
            int kb = kk*8;
            uint32_t a[2][4], b[8][2];
            #pragma unroll
            for (int mt=0; mt<2; mt++){
                int r = wm*32 + mt*16 + gid;
                a[mt][0] = __float_as_uint(As[kb+tig  ][r  ]);
                a[mt][1] = __float_as_uint(As[kb+tig  ][r+8]);
                a[mt][2] = __float_as_uint(As[kb+tig+4][r  ]);
                a[mt][3] = __float_as_uint(As[kb+tig+4][r+8]);
            }
            #pragma unroll
            for (int nt=0; nt<8; nt++){
                int n = wn*64 + nt*8 + gid;
                b[nt][0] = __float_as_uint(Bs[kb+tig  ][n]);
                b[nt][1] = __float_as_uint(Bs[kb+tig+4][n]);
            }
            #pragma unroll
            for (int mt=0; mt<2; mt++){
                #pragma unroll
                for (int nt=0; nt<8; nt++)
                    asm("mma.sync.aligned.m16n8k8.row.col.f32.tf32.tf32.f32 "
                        "{%0,%1,%2,%3}, {%4,%5,%6,%7}, {%8,%9}, {%0,%1,%2,%3};"
                        : "+f"(c[mt][nt][0]), "+f"(c[mt][nt][1]),
                          "+f"(c[mt][nt][2]), "+f"(c[mt][nt][3])
                        : "r"(a[mt][0]), "r"(a[mt][1]), "r"(a[mt][2]), "r"(a[mt][3]),
                          "r"(b[nt][0]), "r"(b[nt][1]));
            }
        }
        __syncthreads();
    }
    #pragma unroll
    for (int mt=0; mt<2; mt++){
        int r = row0 + wm*32 + mt*16 + gid;
        #pragma unroll
        for (int nt=0; nt<8; nt++){
            int cc = col0 + wn*64 + nt*8 + tig*2;
            Cb[(size_t)r*N + cc]       = __float2bfloat16(c[mt][nt][0]);
            Cb[(size_t)r*N + cc + 1]   = __float2bfloat16(c[mt][nt][1]);
            Cb[(size_t)(r+8)*N + cc]   = __float2bfloat16(c[mt][nt][2]);
            Cb[(size_t)(r+8)*N + cc+1] = __float2bfloat16(c[mt][nt][3]);
        }
    }
}

// tiled SGEMM, packed f32x2 FMA (small transition GEMMs)
template<int ACT>
__global__ void sgemm_k(const float* __restrict__ A, const float* __restrict__ Bm,
                        const float* __restrict__ bias, float* __restrict__ C,
                        int M, int N, int K)
{
    const int BM=64, BN=128, BK=16, TM=4, TN=8, THREADS=256;
    __shared__ float As[BM][BK+1];
    __shared__ __align__(16) float Bs[BK][BN];
    int tid = threadIdx.x;
    int tx = tid % (BN/TN), ty = tid / (BN/TN);
    int row0 = blockIdx.y*BM, col0 = blockIdx.x*BN;
    unsigned long long acc2[TM][TN/2];
    #pragma unroll
    for (int m=0;m<TM;m++){
        #pragma unroll
        for (int i=0;i<TN/2;i++) acc2[m][i]=0ull;
    }
    for (int k0 = 0; k0 < K; k0 += BK){
        for (int l = tid; l < BM*BK; l += THREADS){
            int r=l/BK, c=l%BK;
            As[r][c] = A[(size_t)(row0+r)*K + k0 + c];
        }
        for (int l = tid; l < BK*BN; l += THREADS){
            int r=l/BN, c=l%BN, gc=col0+c;
            Bs[r][c] = (gc<N) ? Bm[(size_t)(k0+r)*N + gc] : 0.f;
        }
        __syncthreads();
        #pragma unroll
        for (int kk=0; kk<BK; kk++){
            unsigned long long b2[TN/2];
            #pragma unroll
            for (int i=0;i<TN/2;i++)
                b2[i] = *reinterpret_cast<const unsigned long long*>(&Bs[kk][tx*TN+2*i]);
            #pragma unroll
            for (int m=0;m<TM;m++){
                float av = As[ty*TM+m][kk];
                unsigned long long a2;
                asm("mov.b64 %0, {%1, %1};" : "=l"(a2) : "r"(__float_as_uint(av)));
                #pragma unroll
                for (int i=0;i<TN/2;i++)
                    asm("fma.rn.f32x2 %0, %1, %2, %0;" : "+l"(acc2[m][i]) : "l"(a2), "l"(b2[i]));
            }
        }
        __syncthreads();
    }
    #pragma unroll
    for (int m=0;m<TM;m++){
        int gr = row0 + ty*TM + m;
        #pragma unroll
        for (int i=0;i<TN/2;i++){
            unsigned lo,hi;
            asm("mov.b64 {%0, %1}, %2;" : "=r"(lo), "=r"(hi) : "l"(acc2[m][i]));
            int gc0 = col0 + tx*TN + 2*i;
            if (gc0 < N){
                float v = __uint_as_float(lo);
                if (bias) v += bias[gc0];
                if (ACT) v = tanhf(v);
                C[(size_t)gr*N + gc0] = v;
            }
            if (gc0+1 < N){
                float v = __uint_as_float(hi);
                if (bias) v += bias[gc0+1];
                if (ACT) v = tanhf(v);
                C[(size_t)gr*N + gc0+1] = v;
            }
        }
    }
}

// ---------------- fused LSTM step, 128 blocks: GEMM + gates + state update ----------------
// grid (64 chunks, 2 dirs), 256 threads. Block owns 8 hidden units x full K=512 x 16 batches.
// Wh permuted (c=h*4+g); gpre standard (g*H+h). 32KB smem (reduction aliases h-tile).
__global__ void __launch_bounds__(256) k_lstm_step(const int* __restrict__ lengths, int t){
    int ch = blockIdx.x, dir = blockIdx.y;
    __shared__ __align__(16) float buf[H_*16];     // 32 KB: hsT [k][b]; later red [kq][col][b]
    int tid = threadIdx.x;
    const float* hprev = d_hstate + dir*(B_*H_);
    for (int i = tid; i < H_*16; i += 256){
        int k = i >> 4, b = i & 15;
        buf[i] = hprev[b*H_ + k];
    }
    __syncthreads();

    int col = tid & 31, kq = tid >> 5;             // col 0..31, kq 0..7 (split-K x8)
    const float* wp = d_whP + (size_t)dir*H_*G4_ + (size_t)(kq*64)*G4_ + ch*32 + col;
    unsigned long long acc2[8] = {0,0,0,0,0,0,0,0};
    const unsigned long long* hbase = reinterpret_cast<const unsigned long long*>(&buf[(kq*64)*16]);
    #pragma unroll 4
    for (int k = 0; k < 64; k++){
        float w = wp[(size_t)k*G4_];
        unsigned long long w2;
        asm("mov.b64 %0, {%1, %1};" : "=l"(w2) : "r"(__float_as_uint(w)));
        const unsigned long long* hv = hbase + k*8;
        #pragma unroll
        for (int j=0;j<8;j++)
            asm("fma.rn.f32x2 %0, %1, %2, %0;" : "+l"(acc2[j]) : "l"(hv[j]), "l"(w2));
    }
    __syncthreads();                               // all hsT reads done — safe to alias
    float* red = buf;                              // [kq][col][b] = 8*32*16 floats (16 KB)
    float* rr = &red[(kq*32 + col)*16];
    #pragma unroll
    for (int j=0;j<8;j++){
        unsigned lo,hi;
        asm("mov.b64 {%0, %1}, %2;" : "=r"(lo), "=r"(hi) : "l"(acc2[j]));
        rr[2*j]   = __uint_as_float(lo);
        rr[2*j+1] = __uint_as_float(hi);
    }
    __syncthreads();

    if (tid < 128){
        int hl = tid >> 4, b = tid & 15;
        int hg = ch*8 + hl;
        const float* gpre = (dir ? d_gpre_bw : d_gpre_fw) + (size_t)(b*T_ + t)*G4_;
        float g4[4];
        #pragma unroll
        for (int g = 0; g < 4; g++){
            int cc = hl*4 + g;
            float s = 0.f;
            #pragma unroll
            for (int q = 0; q < 8; q++) s += red[(q*32 + cc)*16 + b];
            g4[g] = s + gpre[g*H_ + hg];
        }
        int idx = (dir*B_ + b)*H_ + hg;
        float cs = d_cstate[idx], hp = d_hstate[idx];
        float cn = sigmf(g4[2] + 1.f)*cs + sigmf(g4[0])*tanhf(g4[1]);
        float hn = sigmf(g4[3])*tanhf(cn);
        int len = lengths[b];
        bool m = (t < len);
        d_cstate[idx] = m ? cn : cs;
        d_hstate[idx] = m ? hn : hp;
        float ho = m ? hn : 0.f;
        if (dir == 0) d_hcat[(size_t)(b*T_ + t)*(2*H_) + hg] = ho;
        else { int p = m ? (len-1-t) : t; d_hcat[(size_t)(b*T_ + p)*(2*H_) + H_ + hg] = ho; }
    }
}

// single-pass online softmax row reduce over 32000 logits
__global__ void k_rowreduce(){
    int row = blockIdx.x, tid = threadIdx.x;
    const float4* p = reinterpret_cast<const float4*>(d_logits + (size_t)row*VS_);
    float m = -1e30f, s = 0.f;
    for (int v = tid; v < VS_/4; v += 256){
        float4 x = p[v];
        #pragma unroll
        for (int q = 0; q < 4; q++){
            float xv = (q==0)?x.x:(q==1)?x.y:(q==2)?x.z:x.w;
            if (xv > m){ s = s*expf(m - xv) + 1.f; m = xv; }
            else        s += expf(xv - m);
        }
    }
    __shared__ float sm[256], ss[256];
    sm[tid] = m; ss[tid] = s; __syncthreads();
    for (int st = 128; st > 0; st >>= 1){
        if (tid < st){
            float m1 = sm[tid], m2 = sm[tid+st];
            float mm = fmaxf(m1, m2);
            ss[tid] = ss[tid]*expf(m1-mm) + ss[tid+st]*expf(m2-mm);
            sm[tid] = mm;
        }
        __syncthreads();
    }
    if (tid == 0){ d_rowmax[row] = sm[0]; d_rowsum[row] = ss[0]; }
}

__global__ void k_nulllogits(const float* __restrict__ Wv, const float* __restrict__ bv){
    __shared__ float ns[H_];
    int tid = threadIdx.x;
    for (int k=tid; k<H_; k+=256) ns[k] = d_nullstate[k];
    __syncthreads();
    int v = blockIdx.x*256 + tid;
    if (v < VS_){
        float a = bv[v];
        #pragma unroll 4
        for (int k=0;k<H_;k++) a = fmaf(ns[k], Wv[(size_t)k*VS_+v], a);
        d_nulllog[v] = a;
    }
}

__global__ void k_nullreduce(){
    __shared__ float sm[1024];
    int tid = threadIdx.x;
    float m = -1e30f;
    for (int v=tid; v<VS_; v+=1024) m = fmaxf(m, d_nulllog[v]);
    sm[tid]=m; __syncthreads();
    for (int s=512;s>0;s>>=1){ if(tid<s) sm[tid]=fmaxf(sm[tid],sm[tid+s]); __syncthreads(); }
    float mx = sm[0]; __syncthreads();
    float su = 0.f;
    for (int v=tid; v<VS_; v+=1024) su += expf(d_nulllog[v]-mx);
    sm[tid]=su; __syncthreads();
    for (int s=512;s>0;s>>=1){ if(tid<s) sm[tid]+=sm[tid+s]; __syncthreads(); }
    if (tid==0){ d_nullred[0]=mx; d_nullred[1]=sm[0]; }
}

__global__ void k_emission(const int* __restrict__ sources, float* __restrict__ out){
    int bt = blockIdx.x, b = bt>>6, t = bt&63, s = threadIdx.x;   // 64
    int col = sources[b*S_+s];
    float l = d_logits[(size_t)bt*VS_ + col];
    out[(size_t)b*(2*T_*S_) + t*S_ + s] = expf(l - d_rowmax[bt]) / d_rowsum[bt];
    out[(size_t)b*(2*T_*S_) + (T_+t)*S_ + s] = expf(d_nulllog[col]-d_nullred[0]) / d_nullred[1];
}

__global__ void k_jsoftmax(){
    int row = blockIdx.x, tid = threadIdx.x;
    float* p = d_jl + (size_t)row*J_;
    __shared__ float sm[256];
    float m = -1e30f;
    for (int j=tid; j<J_; j+=256) m = fmaxf(m, p[j]);
    sm[tid]=m; __syncthreads();
    for (int s=128;s>0;s>>=1){ if(tid<s) sm[tid]=fmaxf(sm[tid],sm[tid+s]); __syncthreads(); }
    float mx = sm[0]; __syncthreads();
    float su = 0.f;
    for (int j=tid; j<J_; j+=256) su += expf(p[j]-mx);
    sm[tid]=su; __syncthreads();
    for (int s=128;s>0;s>>=1){ if(tid<s) sm[tid]+=sm[tid+s]; __syncthreads(); }
    float inv = 1.f/sm[0]; __syncthreads();
    for (int j=tid; j<J_; j+=256) p[j] = expf(p[j]-mx)*inv;
}

__global__ void k_p0(const float* __restrict__ Wp0, const float* __restrict__ bp0){
    int gw = (blockIdx.x*blockDim.x + threadIdx.x) >> 5;
    int lane = threadIdx.x & 31;
    if (gw >= BT_) return;
    float a = 0.f;
    for (int k=lane; k<H_; k+=32) a = fmaf(d_tt[(size_t)gw*H_+k], Wp0[k], a);
    #pragma unroll
    for (int o=16;o>0;o>>=1) a += __shfl_xor_sync(0xffffffffu, a, o);
    if (lane==0) d_p0v[gw] = sigmf(a + bp0[0]);
}

__global__ void k_transition(float* __restrict__ out){
    int b = blockIdx.y;
    int idx = blockIdx.x*256 + threadIdx.x;
    if (idx >= T_*2*T_) return;
    int i = idx / (2*T_), c = idx % (2*T_);
    float tv, lv;
    if (c < T_){
        float jw = d_jl[(size_t)(b*T_+i)*J_ + (MM_ + c - i)];
        tv = jw; lv = logf(jw);
    } else {
        int j = c - T_;
        float p = d_p0v[b*T_+i];
        tv = (i==j) ? p : 0.f;
        lv = (i==j) ? logf(p) : 0.f;
    }
    float* tr  = out + (size_t)B_*2*T_*S_ + (size_t)b*(2*T_*2*T_);
    float* trl = tr + (size_t)B_*2*T_*2*T_;
    tr [i*2*T_ + c] = tv;  tr [(T_+i)*2*T_ + c] = tv;
    trl[i*2*T_ + c] = lv;  trl[(T_+i)*2*T_ + c] = lv;
}

extern "C" void kernel_launch(void* const* d_in, const int* in_sizes, int n_in,
                              void* d_out, int out_size) {
    const int*   sources = (const int*)  d_in[0];
    const int*   targets = (const int*)  d_in[1];
    const int*   tnull   = (const int*)  d_in[2];
    const int*   lengths = (const int*)  d_in[3];
    const float* emb     = (const float*)d_in[4];
    const float* nnW     = (const float*)d_in[5];
    const float* nnb     = (const float*)d_in[6];
    const float* Wx_fw   = (const float*)d_in[7];
    const float* Wh_fw   = (const float*)d_in[8];
    const float* b_fw    = (const float*)d_in[9];
    const float* Wx_bw   = (const float*)d_in[10];
    const float* Wh_bw   = (const float*)d_in[11];
    const float* b_bw    = (const float*)d_in[12];
    const float* Wproj_e = (const float*)d_in[13];
    const float* Wv      = (const float*)d_in[14];
    const float* bv      = (const float*)d_in[15];
    const float* Wproj_t = (const float*)d_in[16];
    const float* Wj      = (const float*)d_in[17];
    const float* bj      = (const float*)d_in[18];
    const float* Wp0     = (const float*)d_in[19];
    const float* bp0     = (const float*)d_in[20];
    float* out = (float*)d_out;

    float *gfw, *gbw, *xp, *xrp, *hc, *lg, *tmp, *ttp, *jl;
    __nv_bfloat16 *tsb, *wvT;
    cudaGetSymbolAddress((void**)&gfw, d_gpre_fw);
    cudaGetSymbolAddress((void**)&gbw, d_gpre_bw);
    cudaGetSymbolAddress((void**)&xp,  d_x);
    cudaGetSymbolAddress((void**)&xrp, d_xrev);
    cudaGetSymbolAddress((void**)&hc,  d_hcat);
    cudaGetSymbolAddress((void**)&lg,  d_logits);
    cudaGetSymbolAddress((void**)&tmp, d_tmpt);
    cudaGetSymbolAddress((void**)&ttp, d_tt);
    cudaGetSymbolAddress((void**)&jl,  d_jl);
    cudaGetSymbolAddress((void**)&tsb, d_tsb);
    cudaGetSymbolAddress((void**)&wvT, d_wvT);

    k_init<<<64,256>>>();
    k_embed<<<BT_,256>>>(targets, lengths, emb);
    k_nullstate<<<1,512>>>(tnull, emb, nnW, nnb);
    k_permwh<<<512,256>>>(Wh_fw, Wh_bw);
    k_cvt_wvT<<<dim3(1000,16),dim3(32,8)>>>(Wv);

    // input projections (tf32, standard gate layout)
    tf32gemm_k<<<dim3(8,16),256>>>(xp,  Wx_fw, b_fw, gfw, BT_, G4_, E_);
    tf32gemm_k<<<dim3(8,16),256>>>(xrp, Wx_bw, b_bw, gbw, BT_, G4_, E_);

    for (int t = 0; t < T_; t++)
        k_lstm_step<<<dim3(64,2),256>>>(lengths, t);

    // emission path: proj_e (tf32 -> bf16 out), logits (bf16 mma.sync)
    tf32gemm_bf16o_k<<<dim3(8,4),256>>>(hc, Wproj_e, tsb, BT_, H_, 2*H_);
    bf16gemm_k<<<dim3(8,250),256>>>(tsb, wvT, bv, lg, BT_, VS_, H_);
    k_rowreduce<<<BT_,256>>>();
    k_nulllogits<<<125,256>>>(Wv, bv);
    k_nullreduce<<<1,1024>>>();
    k_emission<<<BT_,64>>>(sources, out);

    // transition path (fp32, small)
    sgemm_k<0><<<dim3(2,16),256>>>(hc, Wproj_t, nullptr, tmp, BT_, E_, 2*H_);
    sgemm_k<1><<<dim3(4,16),256>>>(tmp, nnW, nnb, ttp, BT_, H_, E_);
    sgemm_k<0><<<dim3(2,16),256>>>(ttp, Wj, bj, jl, BT_, J_, H_);
    k_jsoftmax<<<BT_,256>>>();
    k_p0<<<128,256>>>(Wp0, bp0);
    k_transition<<<dim3(32,16),256>>>(out);
}

// round 13
// speedup vs baseline: 1.6129x; 1.0959x over previous
#include <cuda_runtime.h>
#include <cuda_bf16.h>
#include <cstdint>

#define B_  16
#define S_  64
#define T_  64
#define E_  256
#define H_  512
#define VS_ 32000
#define MM_ 100
#define J_  201
#define BT_ (B_*T_)
#define G4_ (4*H_)

__device__ float d_x[BT_*E_];
__device__ float d_xrev[BT_*E_];
__device__ float d_gpre_fw[BT_*G4_];    // standard layout g*H+h
__device__ float d_gpre_bw[BT_*G4_];
__device__ float d_hstate[2*B_*H_];
__device__ float d_cstate[2*B_*H_];
__device__ float d_hcat[BT_*2*H_];
__device__ float d_logits[(size_t)BT_*VS_];
__device__ float d_rowmax[BT_];
__device__ float d_rowsum[BT_];
__device__ float d_nullstate[H_];
__device__ float d_nulllog[VS_];
__device__ float d_nullred[2];
__device__ float d_tmpt[BT_*E_];
__device__ float d_tt[BT_*H_];
__device__ float d_jl[BT_*J_];
__device__ float d_p0v[BT_];
__device__ __nv_bfloat16 d_tsb[BT_*H_];
__device__ __nv_bfloat16 d_wvT[(size_t)VS_*H_];
__device__ float d_whP[2*H_*G4_];       // [dir][k][c] permuted: c = h*4+g
__device__ unsigned d_bars[T_];         // per-step grid barrier counters

__device__ __forceinline__ float sigmf(float x){ return 1.f/(1.f+expf(-x)); }
__device__ __forceinline__ uint32_t f2tf32(float v){
    uint32_t r; asm("cvt.rna.tf32.f32 %0, %1;" : "=r"(r) : "f"(v)); return r;
}

__global__ void k_init(){
    int i = blockIdx.x*blockDim.x + threadIdx.x;
    if (i < 2*B_*H_){ d_hstate[i]=0.f; d_cstate[i]=0.f; }
    if (i < T_) d_bars[i] = 0u;
}

__global__ void k_embed(const int* __restrict__ targets, const int* __restrict__ lengths,
                        const float* __restrict__ emb){
    int bt = blockIdx.x, b = bt/T_, t = bt%T_;
    int len = lengths[b];
    int rt = (t < len) ? (len-1-t) : t;
    int r0 = targets[bt], r1 = targets[b*T_+rt];
    for (int e = threadIdx.x; e < E_; e += blockDim.x){
        d_x[bt*E_+e]    = emb[(size_t)r0*E_+e];
        d_xrev[bt*E_+e] = emb[(size_t)r1*E_+e];
    }
}

__global__ void k_nullstate(const int* __restrict__ tnull, const float* __restrict__ emb,
                            const float* __restrict__ nnW, const float* __restrict__ nnb){
    __shared__ float xe[E_];
    int tid = threadIdx.x;          // 512
    int r = tnull[0];
    for (int e = tid; e < E_; e += blockDim.x) xe[e] = emb[(size_t)r*E_+e];
    __syncthreads();
    float a = nnb[tid];
    #pragma unroll 4
    for (int e = 0; e < E_; e++) a = fmaf(xe[e], nnW[e*H_+tid], a);
    d_nullstate[tid] = tanhf(a);
}

// permute Wh to gate-interleaved layout: c = h*4+g  <-  g*H+h
__global__ void k_permwh(const float* __restrict__ Whf, const float* __restrict__ Whb){
    int stride = gridDim.x*blockDim.x;
    for (int i = blockIdx.x*blockDim.x + threadIdx.x; i < 2*H_*G4_; i += stride){
        int dir = i / (H_*G4_); int r = (i >> 11) & (H_-1); int c = i & (G4_-1);
        int g = c & 3, h = c >> 2;
        d_whP[i] = (dir ? Whb : Whf)[(size_t)r*G4_ + g*H_ + h];
    }
}

// transpose+convert Wv [H,VS] fp32 -> d_wvT [VS,H] bf16
__global__ void k_cvt_wvT(const float* __restrict__ Wv){
    __shared__ float tile[32][33];
    int nb = blockIdx.x, kb = blockIdx.y;
    int tx = threadIdx.x, ty = threadIdx.y;   // 32 x 8
    #pragma unroll
    for (int i = 0; i < 32; i += 8)
        tile[ty+i][tx] = Wv[(size_t)(kb*32+ty+i)*VS_ + nb*32+tx];
    __syncthreads();
    #pragma unroll
    for (int i = 0; i < 32; i += 8)
        d_wvT[(size_t)(nb*32+ty+i)*H_ + kb*32+tx] = __float2bfloat16(tile[tx][ty+i]);
}

#define CP_ASYNC16(dst, src) \
    asm volatile("cp.async.cg.shared.global [%0], [%1], 16;\n" :: "r"(dst), "l"(src))
#define CP_COMMIT() asm volatile("cp.async.commit_group;\n" ::: "memory")
#define CP_WAIT(n)  asm volatile("cp.async.wait_group %0;\n" :: "n"(n) : "memory")

// ---------------- bf16 mma.sync GEMM (R10, unchanged) ----------------
__global__ void __launch_bounds__(256) bf16gemm_k(const __nv_bfloat16* __restrict__ A,
                                                  const __nv_bfloat16* __restrict__ BT,
                                                  const float* __restrict__ bias,
                                                  float* __restrict__ C,
                                                  int M, int N, int K)
{
    const int BK = 32, LDW = 40;
    __shared__ __align__(16) __nv_bfloat16 As[2][128*LDW];
    __shared__ __align__(16) __nv_bfloat16 Bs[2][128*LDW];
    int tid = threadIdx.x, lane = tid & 31, wid = tid >> 5;
    int wm = wid & 3, wn = wid >> 2;
    int gid = lane >> 2, tig = lane & 3;
    int row0 = blockIdx.x * 128, col0 = blockIdx.y * 128;
    uint32_t sA = (uint32_t)__cvta_generic_to_shared(&As[0][0]);
    uint32_t sB = (uint32_t)__cvta_generic_to_shared(&Bs[0][0]);
    const uint32_t STG = 128*LDW*2;

    int r0s = (tid*2) >> 2, q0 = ((tid*2) & 3)*8;
    int r1s = (tid*2+1) >> 2, q1 = ((tid*2+1) & 3)*8;

    float c[2][8][4];
    #pragma unroll
    for (int mt=0; mt<2; mt++){
        #pragma unroll
        for (int nt=0; nt<8; nt++){
            #pragma unroll
            for (int q=0; q<4; q++) c[mt][nt][q] = 0.f;
        }
    }

    int nch = K / BK;
    {
        CP_ASYNC16(sA + (uint32_t)(r0s*LDW + q0)*2, A + (size_t)(row0 + r0s)*K + q0);
        CP_ASYNC16(sA + (uint32_t)(r1s*LDW + q1)*2, A + (size_t)(row0 + r1s)*K + q1);
        CP_ASYNC16(sB + (uint32_t)(r0s*LDW + q0)*2, BT + (size_t)(col0 + r0s)*K + q0);
        CP_ASYNC16(sB + (uint32_t)(r1s*LDW + q1)*2, BT + (size_t)(col0 + r1s)*K + q1);
        CP_COMMIT();
    }
    int lq = lane >> 3, lr = lane & 7;

    for (int kc = 0; kc < nch; kc++){
        int cur = kc & 1;
        if (kc + 1 < nch){
            int nxt = (kc+1) & 1;
            int k0 = (kc+1)*BK;
            CP_ASYNC16(sA + nxt*STG + (uint32_t)(r0s*LDW + q0)*2, A + (size_t)(row0 + r0s)*K + k0 + q0);
            CP_ASYNC16(sA + nxt*STG + (uint32_t)(r1s*LDW + q1)*2, A + (size_t)(row0 + r1s)*K + k0 + q1);
            CP_ASYNC16(sB + nxt*STG + (uint32_t)(r0s*LDW + q0)*2, BT + (size_t)(col0 + r0s)*K + k0 + q0);
            CP_ASYNC16(sB + nxt*STG + (uint32_t)(r1s*LDW + q1)*2, BT + (size_t)(col0 + r1s)*K + k0 + q1);
            CP_COMMIT();
            CP_WAIT(1);
        } else {
            CP_WAIT(0);
        }
        __syncthreads();
        uint32_t baseA = sA + cur*STG, baseB = sB + cur*STG;
        #pragma unroll
        for (int kk = 0; kk < BK; kk += 16){
            uint32_t a[2][4], b[8][2];
            #pragma unroll
            for (int mt=0; mt<2; mt++){
                int row = wm*32 + mt*16 + (lq&1)*8 + lr;
                int col = kk + (lq>>1)*8;
                uint32_t addr = baseA + (uint32_t)(row*LDW + col)*2;
                asm volatile("ldmatrix.sync.aligned.m8n8.x4.shared.b16 {%0,%1,%2,%3}, [%4];"
                    : "=r"(a[mt][0]), "=r"(a[mt][1]), "=r"(a[mt][2]), "=r"(a[mt][3]) : "r"(addr));
            }
            #pragma unroll
            for (int p=0; p<4; p++){
                int row = wn*64 + p*16 + (lq&1)*8 + lr;
                int col = kk + (lq>>1)*8;
                uint32_t addr = baseB + (uint32_t)(row*LDW + col)*2;
                asm volatile("ldmatrix.sync.aligned.m8n8.x4.shared.b16 {%0,%1,%2,%3}, [%4];"
                    : "=r"(b[2*p][0]), "=r"(b[2*p+1][0]), "=r"(b[2*p][1]), "=r"(b[2*p+1][1]) : "r"(addr));
            }
            #pragma unroll
            for (int mt=0; mt<2; mt++){
                #pragma unroll
                for (int nt=0; nt<8; nt++)
                    asm("mma.sync.aligned.m16n8k16.row.col.f32.bf16.bf16.f32 "
                        "{%0,%1,%2,%3}, {%4,%5,%6,%7}, {%8,%9}, {%0,%1,%2,%3};"
                        : "+f"(c[mt][nt][0]), "+f"(c[mt][nt][1]),
                          "+f"(c[mt][nt][2]), "+f"(c[mt][nt][3])
                        : "r"(a[mt][0]), "r"(a[mt][1]), "r"(a[mt][2]), "r"(a[mt][3]),
                          "r"(b[nt][0]), "r"(b[nt][1]));
            }
        }
        __syncthreads();
    }
    #pragma unroll
    for (int mt=0; mt<2; mt++){
        int r = row0 + wm*32 + mt*16 + gid;
        #pragma unroll
        for (int nt=0; nt<8; nt++){
            int cc = col0 + wn*64 + nt*8 + tig*2;
            float b0 = bias ? bias[cc] : 0.f;
            float b1 = bias ? bias[cc+1] : 0.f;
            C[(size_t)r*N + cc]       = c[mt][nt][0] + b0;
            C[(size_t)r*N + cc + 1]   = c[mt][nt][1] + b1;
            C[(size_t)(r+8)*N + cc]   = c[mt][nt][2] + b0;
            C[(size_t)(r+8)*N + cc+1] = c[mt][nt][3] + b1;
        }
    }
}

// ---------------- tf32 mma.sync GEMM, fp32 out + bias ----------------
__global__ void tf32gemm_k(const float* __restrict__ A, const float* __restrict__ Bm,
                           const float* __restrict__ bias, float* __restrict__ C,
                           int M, int N, int K)
{
    __shared__ float As[16][132];
    __shared__ float Bs[16][132];
    int tid = threadIdx.x, lane = tid & 31, wid = tid >> 5;
    int wm = wid & 3, wn = wid >> 2;
    int gid = lane >> 2, tig = lane & 3;
    int row0 = blockIdx.x * 128, col0 = blockIdx.y * 128;

    float c[2][8][4];
    #pragma unroll
    for (int mt=0; mt<2; mt++){
        #pragma unroll
        for (int nt=0; nt<8; nt++){
            #pragma unroll
            for (int q=0; q<4; q++) c[mt][nt][q] = 0.f;
        }
    }

    for (int k0 = 0; k0 < K; k0 += 16){
        #pragma unroll
        for (int j = 0; j < 2; j++){
            int s = tid*2 + j;
            int r = s >> 2, kq = (s & 3)*4;
            float4 v = *reinterpret_cast<const float4*>(&A[(size_t)(row0 + r)*K + k0 + kq]);
            As[kq+0][r] = __uint_as_float(f2tf32(v.x));
            As[kq+1][r] = __uint_as_float(f2tf32(v.y));
            As[kq+2][r] = __uint_as_float(f2tf32(v.z));
            As[kq+3][r] = __uint_as_float(f2tf32(v.w));
        }
        #pragma unroll
        for (int j = 0; j < 2; j++){
            int s = tid*2 + j;
            int r = s >> 5, c4 = (s & 31)*4;
            float4 v = *reinterpret_cast<const float4*>(&Bm[(size_t)(k0 + r)*N + col0 + c4]);
            Bs[r][c4+0] = __uint_as_float(f2tf32(v.x));
            Bs[r][c4+1] = __uint_as_float(f2tf32(v.y));
            Bs[r][c4+2] = __uint_as_float(f2tf32(v.z));
            Bs[r][c4+3] = __uint_as_float(f2tf32(v.w));
        }
        __syncthreads();
        #pragma unroll
        for (int kk = 0; kk < 2; kk++){
            int kb = kk*8;
            uint32_t a[2][4], b[8][2];
            #pragma unroll
            for (int mt=0; mt<2; mt++){
                int r = wm*32 + mt*16 + gid;
                a[mt][0] = __float_as_uint(As[kb+tig  ][r  ]);
                a[mt][1] = __float_as_uint(As[kb+tig  ][r+8]);
                a[mt][2] = __float_as_uint(As[kb+tig+4][r  ]);
                a[mt][3] = __float_as_uint(As[kb+tig+4][r+8]);
            }
            #pragma unroll
            for (int nt=0; nt<8; nt++){
                int n = wn*64 + nt*8 + gid;
                b[nt][0] = __float_as_uint(Bs[kb+tig  ][n]);
                b[nt][1] = __float_as_uint(Bs[kb+tig+4][n]);
            }
            #pragma unroll
            for (int mt=0; mt<2; mt++){
                #pragma unroll
                for (int nt=0; nt<8; nt++)
                    asm("mma.sync.aligned.m16n8k8.row.col.f32.tf32.tf32.f32 "
                        "{%0,%1,%2,%3}, {%4,%5,%6,%7}, {%8,%9}, {%0,%1,%2,%3};"
                        : "+f"(c[mt][nt][0]), "+f"(c[mt][nt][1]),
                          "+f"(c[mt][nt][2]), "+f"(c[mt][nt][3])
                        : "r"(a[mt][0]), "r"(a[mt][1]), "r"(a[mt][2]), "r"(a[mt][3]),
                          "r"(b[nt][0]), "r"(b[nt][1]));
            }
        }
        __syncthreads();
    }
    #pragma unroll
    for (int mt=0; mt<2; mt++){
        int r = row0 + wm*32 + mt*16 + gid;
        #pragma unroll
        for (int nt=0; nt<8; nt++){
            int cc = col0 + wn*64 + nt*8 + tig*2;
            float b0 = bias ? bias[cc] : 0.f;
            float b1 = bias ? bias[cc+1] : 0.f;
            C[(size_t)r*N + cc]       = c[mt][nt][0] + b0;
            C[(size_t)r*N + cc + 1]   = c[mt][nt][1] + b1;
            C[(size_t)(r+8)*N + cc]   = c[mt][nt][2] + b0;
            C[(size_t)(r+8)*N + cc+1] = c[mt][nt][3] + b1;
        }
    }
}

// ---------------- tf32 mma.sync GEMM, bf16 output (proj_e) ----------------
__global__ void tf32gemm_bf16o_k(const float* __restrict__ A, const float* __restrict__ Bm,
                                 __nv_bfloat16* __restrict__ Cb, int M, int N, int K)
{
    __shared__ float As[16][132];
    __shared__ float Bs[16][132];
    int tid = threadIdx.x, lane = tid & 31, wid = tid >> 5;
    int wm = wid & 3, wn = wid >> 2;
    int gid = lane >> 2, tig = lane & 3;
    int row0 = blockIdx.x * 128, col0 = blockIdx.y * 128;

    float c[2][8][4];
    #pragma unroll
    for (int mt=0; mt<2; mt++){
        #pragma unroll
        for (int nt=0; nt<8; nt++){
            #pragma unroll
            for (int q=0; q<4; q++) c[mt][nt][q] = 0.f;
        }
    }

    for (int k0 = 0; k0 < K; k0 += 16){
        #pragma unroll
        for (int j = 0; j < 2; j++){
            int s = tid*2 + j;
            int r = s >> 2, kq = (s & 3)*4;
            float4 v = *reinterpret_cast<const float4*>(&A[(size_t)(row0 + r)*K + k0 + kq]);
            As[kq+0][r] = __uint_as_float(f2tf32(v.x));
            As[kq+1][r] = __uint_as_float(f2tf32(v.y));
            As[kq+2][r] = __uint_as_float(f2tf32(v.z));
            As[kq+3][r] = __uint_as_float(f2tf32(v.w));
        }
        #pragma unroll
        for (int j = 0; j < 2; j++){
            int s = tid*2 + j;
            int r = s >> 5, c4 = (s & 31)*4;
            float4 v = *reinterpret_cast<const float4*>(&Bm[(size_t)(k0 + r)*N + col0 + c4]);
            Bs[r][c4+0] = __uint_as_float(f2tf32(v.x));
            Bs[r][c4+1] = __uint_as_float(f2tf32(v.y));
            Bs[r][c4+2] = __uint_as_float(f2tf32(v.z));
            Bs[r][c4+3] = __uint_as_float(f2tf32(v.w));
        }
        __syncthreads();
        #pragma unroll
        for (int kk = 0; kk < 2; kk++){
            int kb = kk*8;
            uint32_t a[2][4], b[8][2];
            #pragma unroll
            for (int mt=0; mt<2; mt++){
                int r = wm*32 + mt*16 + gid;
                a[mt][0] = __float_as_uint(As[kb+tig  ][r  ]);
                a[mt][1] = __float_as_uint(As[kb+tig  ][r+8]);
                a[mt][2] = __float_as_uint(As[kb+tig+4][r  ]);
                a[mt][3] = __float_as_uint(As[kb+tig+4][r+8]);
            }
            #pragma unroll
            for (int nt=0; nt<8; nt++){
                int n = wn*64 + nt*8 + gid;
                b[nt][0] = __float_as_uint(Bs[kb+tig  ][n]);
                b[nt][1] = __float_as_uint(Bs[kb+tig+4][n]);
            }
            #pragma unroll
            for (int mt=0; mt<2; mt++){
                #pragma unroll
                for (int nt=0; nt<8; nt++)
                    asm("mma.sync.aligned.m16n8k8.row.col.f32.tf32.tf32.f32 "
                        "{%0,%1,%2,%3}, {%4,%5,%6,%7}, {%8,%9}, {%0,%1,%2,%3};"
                        : "+f"(c[mt][nt][0]), "+f"(c[mt][nt][1]),
                          "+f"(c[mt][nt][2]), "+f"(c[mt][nt][3])
                        : "r"(a[mt][0]), "r"(a[mt][1]), "r"(a[mt][2]), "r"(a[mt][3]),
                          "r"(b[nt][0]), "r"(b[nt][1]));
            }
        }
        __syncthreads();
    }
    #pragma unroll
    for (int mt=0; mt<2; mt++){
        int r = row0 + wm*32 + mt*16 + gid;
        #pragma unroll
        for (int nt=0; nt<8; nt++){
            int cc = col0 + wn*64 + nt*8 + tig*2;
            Cb[(size_t)r*N + cc]       = __float2bfloat16(c[mt][nt][0]);
            Cb[(size_t)r*N + cc + 1]   = __float2bfloat16(c[mt][nt][1]);
            Cb[(size_t)(r+8)*N + cc]   = __float2bfloat16(c[mt][nt][2]);
            Cb[(size_t)(r+8)*N + cc+1] = __float2bfloat16(c[mt][nt][3]);
        }
    }
}

// tiled SGEMM, packed f32x2 FMA (small transition GEMMs)
template<int ACT>
__global__ void sgemm_k(const float* __restrict__ A, const float* __restrict__ Bm,
                        const float* __restrict__ bias, float* __restrict__ C,
                        int M, int N, int K)
{
    const int BM=64, BN=128, BK=16, TM=4, TN=8, THREADS=256;
    __shared__ float As[BM][BK+1];
    __shared__ __align__(16) float Bs[BK][BN];
    int tid = threadIdx.x;
    int tx = tid % (BN/TN), ty = tid / (BN/TN);
    int row0 = blockIdx.y*BM, col0 = blockIdx.x*BN;
    unsigned long long acc2[TM][TN/2];
    #pragma unroll
    for (int m=0;m<TM;m++){
        #pragma unroll
        for (int i=0;i<TN/2;i++) acc2[m][i]=0ull;
    }
    for (int k0 = 0; k0 < K; k0 += BK){
        for (int l = tid; l < BM*BK; l += THREADS){
            int r=l/BK, c=l%BK;
            As[r][c] = A[(size_t)(row0+r)*K + k0 + c];
        }
        for (int l = tid; l < BK*BN; l += THREADS){
            int r=l/BN, c=l%BN, gc=col0+c;
            Bs[r][c] = (gc<N) ? Bm[(size_t)(k0+r)*N + gc] : 0.f;
        }
        __syncthreads();
        #pragma unroll
        for (int kk=0; kk<BK; kk++){
            unsigned long long b2[TN/2];
            #pragma unroll
            for (int i=0;i<TN/2;i++)
                b2[i] = *reinterpret_cast<const unsigned long long*>(&Bs[kk][tx*TN+2*i]);
            #pragma unroll
            for (int m=0;m<TM;m++){
                float av = As[ty*TM+m][kk];
                unsigned long long a2;
                asm("mov.b64 %0, {%1, %1};" : "=l"(a2) : "r"(__float_as_uint(av)));
                #pragma unroll
                for (int i=0;i<TN/2;i++)
                    asm("fma.rn.f32x2 %0, %1, %2, %0;" : "+l"(acc2[m][i]) : "l"(a2), "l"(b2[i]));
            }
        }
        __syncthreads();
    }
    #pragma unroll
    for (int m=0;m<TM;m++){
        int gr = row0 + ty*TM + m;
        #pragma unroll
        for (int i=0;i<TN/2;i++){
            unsigned lo,hi;
            asm("mov.b64 {%0, %1}, %2;" : "=r"(lo), "=r"(hi) : "l"(acc2[m][i]));
            int gc0 = col0 + tx*TN + 2*i;
            if (gc0 < N){
                float v = __uint_as_float(lo);
                if (bias) v += bias[gc0];
                if (ACT) v = tanhf(v);
                C[(size_t)gr*N + gc0] = v;
            }
            if (gc0+1 < N){
                float v = __uint_as_float(hi);
                if (bias) v += bias[gc0+1];
                if (ACT) v = tanhf(v);
                C[(size_t)gr*N + gc0+1] = v;
            }
        }
    }
}

// ---------------- persistent LSTM: all 64 steps in one kernel ----------------
// grid (64,2) = 128 blocks (single wave), 256 threads. Weights register-resident.
// Per-step software grid barrier on d_bars[t] (zeroed each call by k_init).
__global__ void __launch_bounds__(256) k_lstm_all(const int* __restrict__ lengths){
    int ch = blockIdx.x, dir = blockIdx.y;
    __shared__ __align__(16) float buf[H_*16];     // 32 KB: hsT [k][b]; aliased as red
    int tid = threadIdx.x;
    int col = tid & 31, kq = tid >> 5;             // col 0..31, kq 0..7 (split-K x8)

    // hoist recurrent weights into registers (64 per thread)
    float w[64];
    {
        const float* wp = d_whP + (size_t)dir*H_*G4_ + (size_t)(kq*64)*G4_ + ch*32 + col;
        #pragma unroll
        for (int k = 0; k < 64; k++) w[k] = wp[(size_t)k*G4_];
    }
    int hl = tid >> 4, bb = tid & 15;              // combine-stage mapping (tid<128)
    int lenb = (tid < 128) ? lengths[bb] : 0;
    int hg = ch*8 + hl;

    for (int t = 0; t < T_; t++){
        const float* hprev = d_hstate + dir*(B_*H_);
        for (int i = tid; i < H_*16; i += 256){
            int k = i >> 4, b = i & 15;
            buf[i] = hprev[b*H_ + k];
        }
        __syncthreads();

        unsigned long long acc2[8] = {0,0,0,0,0,0,0,0};
        const unsigned long long* hbase = reinterpret_cast<const unsigned long long*>(&buf[(kq*64)*16]);
        #pragma unroll
        for (int k = 0; k < 64; k++){
            unsigned long long w2;
            asm("mov.b64 %0, {%1, %1};" : "=l"(w2) : "r"(__float_as_uint(w[k])));
            const unsigned long long* hv = hbase + k*8;
            #pragma unroll
            for (int j=0;j<8;j++)
                asm("fma.rn.f32x2 %0, %1, %2, %0;" : "+l"(acc2[j]) : "l"(hv[j]), "l"(w2));
        }
        __syncthreads();                           // hsT reads done — safe to alias
        float* red = buf;                          // [kq][col][b] 8*32*16 (16 KB)
        float* rr = &red[(kq*32 + col)*16];
        #pragma unroll
        for (int j=0;j<8;j++){
            unsigned lo,hi;
            asm("mov.b64 {%0, %1}, %2;" : "=r"(lo), "=r"(hi) : "l"(acc2[j]));
            rr[2*j]   = __uint_as_float(lo);
            rr[2*j+1] = __uint_as_float(hi);
        }
        __syncthreads();

        if (tid < 128){
            const float* gpre = (dir ? d_gpre_bw : d_gpre_fw) + (size_t)(bb*T_ + t)*G4_;
            float g4[4];
            #pragma unroll
            for (int g = 0; g < 4; g++){
                int cc = hl*4 + g;
                float s = 0.f;
                #pragma unroll
                for (int q = 0; q < 8; q++) s += red[(q*32 + cc)*16 + bb];
                g4[g] = s + gpre[g*H_ + hg];
            }
            int idx = (dir*B_ + bb)*H_ + hg;
            float cs = d_cstate[idx], hp = d_hstate[idx];
            float cn = sigmf(g4[2] + 1.f)*cs + sigmf(g4[0])*tanhf(g4[1]);
            float hn = sigmf(g4[3])*tanhf(cn);
            bool m = (t < lenb);
            d_cstate[idx] = m ? cn : cs;
            d_hstate[idx] = m ? hn : hp;
            float ho = m ? hn : 0.f;
            if (dir == 0) d_hcat[(size_t)(bb*T_ + t)*(2*H_) + hg] = ho;
            else { int p = m ? (lenb-1-t) : t; d_hcat[(size_t)(bb*T_ + p)*(2*H_) + H_ + hg] = ho; }
        }

        // grid barrier for step t
        __threadfence();                           // publish state writes
        __syncthreads();
        if (tid == 0){
            atomicAdd(&d_bars[t], 1u);
            while (*((volatile unsigned*)&d_bars[t]) < 128u) {}
        }
        __syncthreads();
        __threadfence();                           // invalidate L1 before next h read
    }
}

// single-pass online softmax row reduce over 32000 logits
__global__ void k_rowreduce(){
    int row = blockIdx.x, tid = threadIdx.x;
    const float4* p = reinterpret_cast<const float4*>(d_logits + (size_t)row*VS_);
    float m = -1e30f, s = 0.f;
    for (int v = tid; v < VS_/4; v += 256){
        float4 x = p[v];
        #pragma unroll
        for (int q = 0; q < 4; q++){
            float xv = (q==0)?x.x:(q==1)?x.y:(q==2)?x.z:x.w;
            if (xv > m){ s = s*expf(m - xv) + 1.f; m = xv; }
            else        s += expf(xv - m);
        }
    }
    __shared__ float sm[256], ss[256];
    sm[tid] = m; ss[tid] = s; __syncthreads();
    for (int st = 128; st > 0; st >>= 1){
        if (tid < st){
            float m1 = sm[tid], m2 = sm[tid+st];
            float mm = fmaxf(m1, m2);
            ss[tid] = ss[tid]*expf(m1-mm) + ss[tid+st]*expf(m2-mm);
            sm[tid] = mm;
        }
        __syncthreads();
    }
    if (tid == 0){ d_rowmax[row] = sm[0]; d_rowsum[row] = ss[0]; }
}

__global__ void k_nulllogits(const float* __restrict__ Wv, const float* __restrict__ bv){
    __shared__ float ns[H_];
    int tid = threadIdx.x;
    for (int k=tid; k<H_; k+=256) ns[k] = d_nullstate[k];
    __syncthreads();
    int v = blockIdx.x*256 + tid;
    if (v < VS_){
        float a = bv[v];
        #pragma unroll 4
        for (int k=0;k<H_;k++) a = fmaf(ns[k], Wv[(size_t)k*VS_+v], a);
        d_nulllog[v] = a;
    }
}

__global__ void k_nullreduce(){
    __shared__ float sm[1024];
    int tid = threadIdx.x;
    float m = -1e30f;
    for (int v=tid; v<VS_; v+=1024) m = fmaxf(m, d_nulllog[v]);
    sm[tid]=m; __syncthreads();
    for (int s=512;s>0;s>>=1){ if(tid<s) sm[tid]=fmaxf(sm[tid],sm[tid+s]); __syncthreads(); }
    float mx = sm[0]; __syncthreads();
    float su = 0.f;
    for (int v=tid; v<VS_; v+=1024) su += expf(d_nulllog[v]-mx);
    sm[tid]=su; __syncthreads();
    for (int s=512;s>0;s>>=1){ if(tid<s) sm[tid]+=sm[tid+s]; __syncthreads(); }
    if (tid==0){ d_nullred[0]=mx; d_nullred[1]=sm[0]; }
}

__global__ void k_emission(const int* __restrict__ sources, float* __restrict__ out){
    int bt = blockIdx.x, b = bt>>6, t = bt&63, s = threadIdx.x;   // 64
    int col = sources[b*S_+s];
    float l = d_logits[(size_t)bt*VS_ + col];
    out[(size_t)b*(2*T_*S_) + t*S_ + s] = expf(l - d_rowmax[bt]) / d_rowsum[bt];
    out[(size_t)b*(2*T_*S_) + (T_+t)*S_ + s] = expf(d_nulllog[col]-d_nullred[0]) / d_nullred[1];
}

__global__ void k_jsoftmax(){
    int row = blockIdx.x, tid = threadIdx.x;
    float* p = d_jl + (size_t)row*J_;
    __shared__ float sm[256];
    float m = -1e30f;
    for (int j=tid; j<J_; j+=256) m = fmaxf(m, p[j]);
    sm[tid]=m; __syncthreads();
    for (int s=128;s>0;s>>=1){ if(tid<s) sm[tid]=fmaxf(sm[tid],sm[tid+s]); __syncthreads(); }
    float mx = sm[0]; __syncthreads();
    float su = 0.f;
    for (int j=tid; j<J_; j+=256) su += expf(p[j]-mx);
    sm[tid]=su; __syncthreads();
    for (int s=128;s>0;s>>=1){ if(tid<s) sm[tid]+=sm[tid+s]; __syncthreads(); }
    float inv = 1.f/sm[0]; __syncthreads();
    for (int j=tid; j<J_; j+=256) p[j] = expf(p[j]-mx)*inv;
}

__global__ void k_p0(const float* __restrict__ Wp0, const float* __restrict__ bp0){
    int gw = (blockIdx.x*blockDim.x + threadIdx.x) >> 5;
    int lane = threadIdx.x & 31;
    if (gw >= BT_) return;
    float a = 0.f;
    for (int k=lane; k<H_; k+=32) a = fmaf(d_tt[(size_t)gw*H_+k], Wp0[k], a);
    #pragma unroll
    for (int o=16;o>0;o>>=1) a += __shfl_xor_sync(0xffffffffu, a, o);
    if (lane==0) d_p0v[gw] = sigmf(a + bp0[0]);
}

__global__ void k_transition(float* __restrict__ out){
    int b = blockIdx.y;
    int idx = blockIdx.x*256 + threadIdx.x;
    if (idx >= T_*2*T_) return;
    int i = idx / (2*T_), c = idx % (2*T_);
    float tv, lv;
    if (c < T_){
        float jw = d_jl[(size_t)(b*T_+i)*J_ + (MM_ + c - i)];
        tv = jw; lv = logf(jw);
    } else {
        int j = c - T_;
        float p = d_p0v[b*T_+i];
        tv = (i==j) ? p : 0.f;
        lv = (i==j) ? logf(p) : 0.f;
    }
    float* tr  = out + (size_t)B_*2*T_*S_ + (size_t)b*(2*T_*2*T_);
    float* trl = tr + (size_t)B_*2*T_*2*T_;
    tr [i*2*T_ + c] = tv;  tr [(T_+i)*2*T_ + c] = tv;
    trl[i*2*T_ + c] = lv;  trl[(T_+i)*2*T_ + c] = lv;
}

extern "C" void kernel_launch(void* const* d_in, const int* in_sizes, int n_in,
                              void* d_out, int out_size) {
    const int*   sources = (const int*)  d_in[0];
    const int*   targets = (const int*)  d_in[1];
    const int*   tnull   = (const int*)  d_in[2];
    const int*   lengths = (const int*)  d_in[3];
    const float* emb     = (const float*)d_in[4];
    const float* nnW     = (const float*)d_in[5];
    const float* nnb     = (const float*)d_in[6];
    const float* Wx_fw   = (const float*)d_in[7];
    const float* Wh_fw   = (const float*)d_in[8];
    const float* b_fw    = (const float*)d_in[9];
    const float* Wx_bw   = (const float*)d_in[10];
    const float* Wh_bw   = (const float*)d_in[11];
    const float* b_bw    = (const float*)d_in[12];
    const float* Wproj_e = (const float*)d_in[13];
    const float* Wv      = (const float*)d_in[14];
    const float* bv      = (const float*)d_in[15];
    const float* Wproj_t = (const float*)d_in[16];
    const float* Wj      = (const float*)d_in[17];
    const float* bj      = (const float*)d_in[18];
    const float* Wp0     = (const float*)d_in[19];
    const float* bp0     = (const float*)d_in[20];
    float* out = (float*)d_out;

    float *gfw, *gbw, *xp, *xrp, *hc, *lg, *tmp, *ttp, *jl;
    __nv_bfloat16 *tsb, *wvT;
    cudaGetSymbolAddress((void**)&gfw, d_gpre_fw);
    cudaGetSymbolAddress((void**)&gbw, d_gpre_bw);
    cudaGetSymbolAddress((void**)&xp,  d_x);
    cudaGetSymbolAddress((void**)&xrp, d_xrev);
    cudaGetSymbolAddress((void**)&hc,  d_hcat);
    cudaGetSymbolAddress((void**)&lg,  d_logits);
    cudaGetSymbolAddress((void**)&tmp, d_tmpt);
    cudaGetSymbolAddress((void**)&ttp, d_tt);
    cudaGetSymbolAddress((void**)&jl,  d_jl);
    cudaGetSymbolAddress((void**)&tsb, d_tsb);
    cudaGetSymbolAddress((void**)&wvT, d_wvT);

    k_init<<<64,256>>>();
    k_embed<<<BT_,256>>>(targets, lengths, emb);
    k_nullstate<<<1,512>>>(tnull, emb, nnW, nnb);
    k_permwh<<<512,256>>>(Wh_fw, Wh_bw);
    k_cvt_wvT<<<dim3(1000,16),dim3(32,8)>>>(Wv);

    // input projections (tf32, standard gate layout)
    tf32gemm_k<<<dim3(8,16),256>>>(xp,  Wx_fw, b_fw, gfw, BT_, G4_, E_);
    tf32gemm_k<<<dim3(8,16),256>>>(xrp, Wx_bw, b_bw, gbw, BT_, G4_, E_);

    // persistent LSTM (all 64 timesteps, internal grid barriers)
    k_lstm_all<<<dim3(64,2),256>>>(lengths);

    // emission path: proj_e (tf32 -> bf16 out), logits (bf16 mma.sync)
    tf32gemm_bf16o_k<<<dim3(8,4),256>>>(hc, Wproj_e, tsb, BT_, H_, 2*H_);
    bf16gemm_k<<<dim3(8,250),256>>>(tsb, wvT, bv, lg, BT_, VS_, H_);
    k_rowreduce<<<BT_,256>>>();
    k_nulllogits<<<125,256>>>(Wv, bv);
    k_nullreduce<<<1,1024>>>();
    k_emission<<<BT_,64>>>(sources, out);

    // transition path (fp32, small)
    sgemm_k<0><<<dim3(2,16),256>>>(hc, Wproj_t, nullptr, tmp, BT_, E_, 2*H_);
    sgemm_k<1><<<dim3(4,16),256>>>(tmp, nnW, nnb, ttp, BT_, H_, E_);
    sgemm_k<0><<<dim3(2,16),256>>>(ttp, Wj, bj, jl, BT_, J_, H_);
    k_jsoftmax<<<BT_,256>>>();
    k_p0<<<128,256>>>(Wp0, bp0);
    k_transition<<<dim3(32,16),256>>>(out);
}

// round 14
// speedup vs baseline: 1.8610x; 1.1538x over previous
#include <cuda_runtime.h>
#include <cuda_bf16.h>
#include <cstdint>

#define B_  16
#define S_  64
#define T_  64
#define E_  256
#define H_  512
#define VS_ 32000
#define MM_ 100
#define J_  201
#define BT_ (B_*T_)
#define G4_ (4*H_)

__device__ float d_x[BT_*E_];
__device__ float d_xrev[BT_*E_];
__device__ float d_gpre_fw[BT_*G4_];
__device__ float d_gpre_bw[BT_*G4_];
__device__ float d_hstate[2*B_*H_];
__device__ float d_cstate[2*B_*H_];
__device__ float d_hcat[BT_*2*H_];
__device__ float d_logits[(size_t)BT_*VS_];
__device__ float d_rowmax[BT_];
__device__ float d_rowsum[BT_];
__device__ float d_nullstate[H_];
__device__ float d_nulllog[VS_];
__device__ float d_nullred[2];
__device__ float d_tmpt[BT_*E_];
__device__ float d_tt[BT_*H_];
__device__ float d_jl[BT_*J_];
__device__ float d_p0v[BT_];
__device__ __nv_bfloat16 d_tsb[BT_*H_];
__device__ __nv_bfloat16 d_wvT[(size_t)VS_*H_];
__device__ float d_whP[2*H_*G4_];       // [dir][k][c] permuted: c = h*4+g
__device__ unsigned d_bars[T_];

__device__ __forceinline__ float sigmf(float x){ return 1.f/(1.f+expf(-x)); }
__device__ __forceinline__ uint32_t f2tf32(float v){
    uint32_t r; asm("cvt.rna.tf32.f32 %0, %1;" : "=r"(r) : "f"(v)); return r;
}

__global__ void k_init(){
    int i = blockIdx.x*blockDim.x + threadIdx.x;
    if (i < 2*B_*H_){ d_hstate[i]=0.f; d_cstate[i]=0.f; }
    if (i < T_) d_bars[i] = 0u;
}

__global__ void k_embed(const int* __restrict__ targets, const int* __restrict__ lengths,
                        const float* __restrict__ emb){
    int bt = blockIdx.x, b = bt/T_, t = bt%T_;
    int len = lengths[b];
    int rt = (t < len) ? (len-1-t) : t;
    int r0 = targets[bt], r1 = targets[b*T_+rt];
    for (int e = threadIdx.x; e < E_; e += blockDim.x){
        d_x[bt*E_+e]    = emb[(size_t)r0*E_+e];
        d_xrev[bt*E_+e] = emb[(size_t)r1*E_+e];
    }
}

__global__ void k_nullstate(const int* __restrict__ tnull, const float* __restrict__ emb,
                            const float* __restrict__ nnW, const float* __restrict__ nnb){
    __shared__ float xe[E_];
    int tid = threadIdx.x;          // 512
    int r = tnull[0];
    for (int e = tid; e < E_; e += blockDim.x) xe[e] = emb[(size_t)r*E_+e];
    __syncthreads();
    float a = nnb[tid];
    #pragma unroll 4
    for (int e = 0; e < E_; e++) a = fmaf(xe[e], nnW[e*H_+tid], a);
    d_nullstate[tid] = tanhf(a);
}

__global__ void k_permwh(const float* __restrict__ Whf, const float* __restrict__ Whb){
    int stride = gridDim.x*blockDim.x;
    for (int i = blockIdx.x*blockDim.x + threadIdx.x; i < 2*H_*G4_; i += stride){
        int dir = i / (H_*G4_); int r = (i >> 11) & (H_-1); int c = i & (G4_-1);
        int g = c & 3, h = c >> 2;
        d_whP[i] = (dir ? Whb : Whf)[(size_t)r*G4_ + g*H_ + h];
    }
}

__global__ void k_cvt_wvT(const float* __restrict__ Wv){
    __shared__ float tile[32][33];
    int nb = blockIdx.x, kb = blockIdx.y;
    int tx = threadIdx.x, ty = threadIdx.y;   // 32 x 8
    #pragma unroll
    for (int i = 0; i < 32; i += 8)
        tile[ty+i][tx] = Wv[(size_t)(kb*32+ty+i)*VS_ + nb*32+tx];
    __syncthreads();
    #pragma unroll
    for (int i = 0; i < 32; i += 8)
        d_wvT[(size_t)(nb*32+ty+i)*H_ + kb*32+tx] = __float2bfloat16(tile[tx][ty+i]);
}

#define CP_ASYNC16(dst, src) \
    asm volatile("cp.async.cg.shared.global [%0], [%1], 16;\n" :: "r"(dst), "l"(src))
#define CP_COMMIT() asm volatile("cp.async.commit_group;\n" ::: "memory")
#define CP_WAIT(n)  asm volatile("cp.async.wait_group %0;\n" :: "n"(n) : "memory")

// ---------------- bf16 mma.sync GEMM, compile-time K (full unroll) ----------------
template<int KV>
__global__ void __launch_bounds__(256) bf16gemm_k(const __nv_bfloat16* __restrict__ A,
                                                  const __nv_bfloat16* __restrict__ BT,
                                                  const float* __restrict__ bias,
                                                  float* __restrict__ C,
                                                  int M, int N)
{
    const int BK = 32, LDW = 40, NCH = KV/BK;
    __shared__ __align__(16) __nv_bfloat16 As[2][128*LDW];
    __shared__ __align__(16) __nv_bfloat16 Bs[2][128*LDW];
    int tid = threadIdx.x, lane = tid & 31, wid = tid >> 5;
    int wm = wid & 3, wn = wid >> 2;
    int gid = lane >> 2, tig = lane & 3;
    int row0 = blockIdx.x * 128, col0 = blockIdx.y * 128;
    uint32_t sA = (uint32_t)__cvta_generic_to_shared(&As[0][0]);
    uint32_t sB = (uint32_t)__cvta_generic_to_shared(&Bs[0][0]);
    const uint32_t STG = 128*LDW*2;

    int r0s = (tid*2) >> 2, q0 = ((tid*2) & 3)*8;
    int r1s = (tid*2+1) >> 2, q1 = ((tid*2+1) & 3)*8;
    const __nv_bfloat16* ga0 = A + (size_t)(row0 + r0s)*KV + q0;
    const __nv_bfloat16* ga1 = A + (size_t)(row0 + r1s)*KV + q1;
    const __nv_bfloat16* gb0 = BT + (size_t)(col0 + r0s)*KV + q0;
    const __nv_bfloat16* gb1 = BT + (size_t)(col0 + r1s)*KV + q1;
    uint32_t a0d = (uint32_t)(r0s*LDW + q0)*2, a1d = (uint32_t)(r1s*LDW + q1)*2;

    float c[2][8][4];
    #pragma unroll
    for (int mt=0; mt<2; mt++){
        #pragma unroll
        for (int nt=0; nt<8; nt++){
            #pragma unroll
            for (int q=0; q<4; q++) c[mt][nt][q] = 0.f;
        }
    }

    CP_ASYNC16(sA + a0d, ga0);
    CP_ASYNC16(sA + a1d, ga1);
    CP_ASYNC16(sB + a0d, gb0);
    CP_ASYNC16(sB + a1d, gb1);
    CP_COMMIT();
    int lq = lane >> 3, lr = lane & 7;

    #pragma unroll
    for (int kc = 0; kc < NCH; kc++){
        int cur = kc & 1;
        if (kc + 1 < NCH){
            int nxt = (kc+1) & 1;
            int k0 = (kc+1)*BK;
            CP_ASYNC16(sA + nxt*STG + a0d, ga0 + k0);
            CP_ASYNC16(sA + nxt*STG + a1d, ga1 + k0);
            CP_ASYNC16(sB + nxt*STG + a0d, gb0 + k0);
            CP_ASYNC16(sB + nxt*STG + a1d, gb1 + k0);
            CP_COMMIT();
            CP_WAIT(1);
        } else {
            CP_WAIT(0);
        }
        __syncthreads();
        uint32_t baseA = sA + cur*STG, baseB = sB + cur*STG;
        #pragma unroll
        for (int kk = 0; kk < BK; kk += 16){
            uint32_t a[2][4], b[8][2];
            #pragma unroll
            for (int mt=0; mt<2; mt++){
                int row = wm*32 + mt*16 + (lq&1)*8 + lr;
                int col = kk + (lq>>1)*8;
                uint32_t addr = baseA + (uint32_t)(row*LDW + col)*2;
                asm volatile("ldmatrix.sync.aligned.m8n8.x4.shared.b16 {%0,%1,%2,%3}, [%4];"
                    : "=r"(a[mt][0]), "=r"(a[mt][1]), "=r"(a[mt][2]), "=r"(a[mt][3]) : "r"(addr));
            }
            #pragma unroll
            for (int p=0; p<4; p++){
                int row = wn*64 + p*16 + (lq&1)*8 + lr;
                int col = kk + (lq>>1)*8;
                uint32_t addr = baseB + (uint32_t)(row*LDW + col)*2;
                asm volatile("ldmatrix.sync.aligned.m8n8.x4.shared.b16 {%0,%1,%2,%3}, [%4];"
                    : "=r"(b[2*p][0]), "=r"(b[2*p+1][0]), "=r"(b[2*p][1]), "=r"(b[2*p+1][1]) : "r"(addr));
            }
            #pragma unroll
            for (int mt=0; mt<2; mt++){
                #pragma unroll
                for (int nt=0; nt<8; nt++)
                    asm("mma.sync.aligned.m16n8k16.row.col.f32.bf16.bf16.f32 "
                        "{%0,%1,%2,%3}, {%4,%5,%6,%7}, {%8,%9}, {%0,%1,%2,%3};"
                        : "+f"(c[mt][nt][0]), "+f"(c[mt][nt][1]),
                          "+f"(c[mt][nt][2]), "+f"(c[mt][nt][3])
                        : "r"(a[mt][0]), "r"(a[mt][1]), "r"(a[mt][2]), "r"(a[mt][3]),
                          "r"(b[nt][0]), "r"(b[nt][1]));
            }
        }
        __syncthreads();
    }
    #pragma unroll
    for (int mt=0; mt<2; mt++){
        int r = row0 + wm*32 + mt*16 + gid;
        #pragma unroll
        for (int nt=0; nt<8; nt++){
            int cc = col0 + wn*64 + nt*8 + tig*2;
            float b0 = bias ? bias[cc] : 0.f;
            float b1 = bias ? bias[cc+1] : 0.f;
            C[(size_t)r*N + cc]       = c[mt][nt][0] + b0;
            C[(size_t)r*N + cc + 1]   = c[mt][nt][1] + b1;
            C[(size_t)(r+8)*N + cc]   = c[mt][nt][2] + b0;
            C[(size_t)(r+8)*N + cc+1] = c[mt][nt][3] + b1;
        }
    }
}

// ---------------- tf32 mma.sync GEMM, fp32 out + bias (+tanh if ACT) ----------------
template<int ACT>
__global__ void tf32gemm_k(const float* __restrict__ A, const float* __restrict__ Bm,
                           const float* __restrict__ bias, float* __restrict__ C,
                           int M, int N, int K)
{
    __shared__ float As[16][132];
    __shared__ float Bs[16][132];
    int tid = threadIdx.x, lane = tid & 31, wid = tid >> 5;
    int wm = wid & 3, wn = wid >> 2;
    int gid = lane >> 2, tig = lane & 3;
    int row0 = blockIdx.x * 128, col0 = blockIdx.y * 128;

    float c[2][8][4];
    #pragma unroll
    for (int mt=0; mt<2; mt++){
        #pragma unroll
        for (int nt=0; nt<8; nt++){
            #pragma unroll
            for (int q=0; q<4; q++) c[mt][nt][q] = 0.f;
        }
    }

    for (int k0 = 0; k0 < K; k0 += 16){
        #pragma unroll
        for (int j = 0; j < 2; j++){
            int s = tid*2 + j;
            int r = s >> 2, kq = (s & 3)*4;
            float4 v = *reinterpret_cast<const float4*>(&A[(size_t)(row0 + r)*K + k0 + kq]);
            As[kq+0][r] = __uint_as_float(f2tf32(v.x));
            As[kq+1][r] = __uint_as_float(f2tf32(v.y));
            As[kq+2][r] = __uint_as_float(f2tf32(v.z));
            As[kq+3][r] = __uint_as_float(f2tf32(v.w));
        }
        #pragma unroll
        for (int j = 0; j < 2; j++){
            int s = tid*2 + j;
            int r = s >> 5, c4 = (s & 31)*4;
            float4 v = *reinterpret_cast<const float4*>(&Bm[(size_t)(k0 + r)*N + col0 + c4]);
            Bs[r][c4+0] = __uint_as_float(f2tf32(v.x));
            Bs[r][c4+1] = __uint_as_float(f2tf32(v.y));
            Bs[r][c4+2] = __uint_as_float(f2tf32(v.z));
            Bs[r][c4+3] = __uint_as_float(f2tf32(v.w));
        }
        __syncthreads();
        #pragma unroll
        for (int kk = 0; kk < 2; kk++){
            int kb = kk*8;
            uint32_t a[2][4], b[8][2];
            #pragma unroll
            for (int mt=0; mt<2; mt++){
                int r = wm*32 + mt*16 + gid;
                a[mt][0] = __float_as_uint(As[kb+tig  ][r  ]);
                a[mt][1] = __float_as_uint(As[kb+tig  ][r+8]);
                a[mt][2] = __float_as_uint(As[kb+tig+4][r  ]);
                a[mt][3] = __float_as_uint(As[kb+tig+4][r+8]);
            }
            #pragma unroll
            for (int nt=0; nt<8; nt++){
                int n = wn*64 + nt*8 + gid;
                b[nt][0] = __float_as_uint(Bs[kb+tig  ][n]);
                b[nt][1] = __float_as_uint(Bs[kb+tig+4][n]);
            }
            #pragma unroll
            for (int mt=0; mt<2; mt++){
                #pragma unroll
                for (int nt=0; nt<8; nt++)
                    asm("mma.sync.aligned.m16n8k8.row.col.f32.tf32.tf32.f32 "
                        "{%0,%1,%2,%3}, {%4,%5,%6,%7}, {%8,%9}, {%0,%1,%2,%3};"
                        : "+f"(c[mt][nt][0]), "+f"(c[mt][nt][1]),
                          "+f"(c[mt][nt][2]), "+f"(c[mt][nt][3])
                        : "r"(a[mt][0]), "r"(a[mt][1]), "r"(a[mt][2]), "r"(a[mt][3]),
                          "r"(b[nt][0]), "r"(b[nt][1]));
            }
        }
        __syncthreads();
    }
    #pragma unroll
    for (int mt=0; mt<2; mt++){
        int r = row0 + wm*32 + mt*16 + gid;
        #pragma unroll
        for (int nt=0; nt<8; nt++){
            int cc = col0 + wn*64 + nt*8 + tig*2;
            float b0 = bias ? bias[cc] : 0.f;
            float b1 = bias ? bias[cc+1] : 0.f;
            float v0 = c[mt][nt][0] + b0, v1 = c[mt][nt][1] + b1;
            float v2 = c[mt][nt][2] + b0, v3 = c[mt][nt][3] + b1;
            if (ACT){ v0=tanhf(v0); v1=tanhf(v1); v2=tanhf(v2); v3=tanhf(v3); }
            C[(size_t)r*N + cc]       = v0;
            C[(size_t)r*N + cc + 1]   = v1;
            C[(size_t)(r+8)*N + cc]   = v2;
            C[(size_t)(r+8)*N + cc+1] = v3;
        }
    }
}

// ---------------- tf32 mma.sync GEMM, bf16 output (proj_e) ----------------
__global__ void tf32gemm_bf16o_k(const float* __restrict__ A, const float* __restrict__ Bm,
                                 __nv_bfloat16* __restrict__ Cb, int M, int N, int K)
{
    __shared__ float As[16][132];
    __shared__ float Bs[16][132];
    int tid = threadIdx.x, lane = tid & 31, wid = tid >> 5;
    int wm = wid & 3, wn = wid >> 2;
    int gid = lane >> 2, tig = lane & 3;
    int row0 = blockIdx.x * 128, col0 = blockIdx.y * 128;

    float c[2][8][4];
    #pragma unroll
    for (int mt=0; mt<2; mt++){
        #pragma unroll
        for (int nt=0; nt<8; nt++){
            #pragma unroll
            for (int q=0; q<4; q++) c[mt][nt][q] = 0.f;
        }
    }

    for (int k0 = 0; k0 < K; k0 += 16){
        #pragma unroll
        for (int j = 0; j < 2; j++){
            int s = tid*2 + j;
            int r = s >> 2, kq = (s & 3)*4;
            float4 v = *reinterpret_cast<const float4*>(&A[(size_t)(row0 + r)*K + k0 + kq]);
            As[kq+0][r] = __uint_as_float(f2tf32(v.x));
            As[kq+1][r] = __uint_as_float(f2tf32(v.y));
            As[kq+2][r] = __uint_as_float(f2tf32(v.z));
            As[kq+3][r] = __uint_as_float(f2tf32(v.w));
        }
        #pragma unroll
        for (int j = 0; j < 2; j++){
            int s = tid*2 + j;
            int r = s >> 5, c4 = (s & 31)*4;
            float4 v = *reinterpret_cast<const float4*>(&Bm[(size_t)(k0 + r)*N + col0 + c4]);
            Bs[r][c4+0] = __uint_as_float(f2tf32(v.x));
            Bs[r][c4+1] = __uint_as_float(f2tf32(v.y));
            Bs[r][c4+2] = __uint_as_float(f2tf32(v.z));
            Bs[r][c4+3] = __uint_as_float(f2tf32(v.w));
        }
        __syncthreads();
        #pragma unroll
        for (int kk = 0; kk < 2; kk++){
            int kb = kk*8;
            uint32_t a[2][4], b[8][2];
            #pragma unroll
            for (int mt=0; mt<2; mt++){
                int r = wm*32 + mt*16 + gid;
                a[mt][0] = __float_as_uint(As[kb+tig  ][r  ]);
                a[mt][1] = __float_as_uint(As[kb+tig  ][r+8]);
                a[mt][2] = __float_as_uint(As[kb+tig+4][r  ]);
                a[mt][3] = __float_as_uint(As[kb+tig+4][r+8]);
            }
            #pragma unroll
            for (int nt=0; nt<8; nt++){
                int n = wn*64 + nt*8 + gid;
                b[nt][0] = __float_as_uint(Bs[kb+tig  ][n]);
                b[nt][1] = __float_as_uint(Bs[kb+tig+4][n]);
            }
            #pragma unroll
            for (int mt=0; mt<2; mt++){
                #pragma unroll
                for (int nt=0; nt<8; nt++)
                    asm("mma.sync.aligned.m16n8k8.row.col.f32.tf32.tf32.f32 "
                        "{%0,%1,%2,%3}, {%4,%5,%6,%7}, {%8,%9}, {%0,%1,%2,%3};"
                        : "+f"(c[mt][nt][0]), "+f"(c[mt][nt][1]),
                          "+f"(c[mt][nt][2]), "+f"(c[mt][nt][3])
                        : "r"(a[mt][0]), "r"(a[mt][1]), "r"(a[mt][2]), "r"(a[mt][3]),
                          "r"(b[nt][0]), "r"(b[nt][1]));
            }
        }
        __syncthreads();
    }
    #pragma unroll
    for (int mt=0; mt<2; mt++){
        int r = row0 + wm*32 + mt*16 + gid;
        #pragma unroll
        for (int nt=0; nt<8; nt++){
            int cc = col0 + wn*64 + nt*8 + tig*2;
            Cb[(size_t)r*N + cc]       = __float2bfloat16(c[mt][nt][0]);
            Cb[(size_t)r*N + cc + 1]   = __float2bfloat16(c[mt][nt][1]);
            Cb[(size_t)(r+8)*N + cc]   = __float2bfloat16(c[mt][nt][2]);
            Cb[(size_t)(r+8)*N + cc+1] = __float2bfloat16(c[mt][nt][3]);
        }
    }
}

// tiled SGEMM, packed f32x2 FMA (N=201 GEMM)
template<int ACT>
__global__ void sgemm_k(const float* __restrict__ A, const float* __restrict__ Bm,
                        const float* __restrict__ bias, float* __restrict__ C,
                        int M, int N, int K)
{
    const int BM=64, BN=128, BK=16, TM=4, TN=8, THREADS=256;
    __shared__ float As[BM][BK+1];
    __shared__ __align__(16) float Bs[BK][BN];
    int tid = threadIdx.x;
    int tx = tid % (BN/TN), ty = tid / (BN/TN);
    int row0 = blockIdx.y*BM, col0 = blockIdx.x*BN;
    unsigned long long acc2[TM][TN/2];
    #pragma unroll
    for (int m=0;m<TM;m++){
        #pragma unroll
        for (int i=0;i<TN/2;i++) acc2[m][i]=0ull;
    }
    for (int k0 = 0; k0 < K; k0 += BK){
        for (int l = tid; l < BM*BK; l += THREADS){
            int r=l/BK, c=l%BK;
            As[r][c] = A[(size_t)(row0+r)*K + k0 + c];
        }
        for (int l = tid; l < BK*BN; l += THREADS){
            int r=l/BN, c=l%BN, gc=col0+c;
            Bs[r][c] = (gc<N) ? Bm[(size_t)(k0+r)*N + gc] : 0.f;
        }
        __syncthreads();
        #pragma unroll
        for (int kk=0; kk<BK; kk++){
            unsigned long long b2[TN/2];
            #pragma unroll
            for (int i=0;i<TN/2;i++)
                b2[i] = *reinterpret_cast<const unsigned long long*>(&Bs[kk][tx*TN+2*i]);
            #pragma unroll
            for (int m=0;m<TM;m++){
                float av = As[ty*TM+m][kk];
                unsigned long long a2;
                asm("mov.b64 %0, {%1, %1};" : "=l"(a2) : "r"(__float_as_uint(av)));
                #pragma unroll
                for (int i=0;i<TN/2;i++)
                    asm("fma.rn.f32x2 %0, %1, %2, %0;" : "+l"(acc2[m][i]) : "l"(a2), "l"(b2[i]));
            }
        }
        __syncthreads();
    }
    #pragma unroll
    for (int m=0;m<TM;m++){
        int gr = row0 + ty*TM + m;
        #pragma unroll
        for (int i=0;i<TN/2;i++){
            unsigned lo,hi;
            asm("mov.b64 {%0, %1}, %2;" : "=r"(lo), "=r"(hi) : "l"(acc2[m][i]));
            int gc0 = col0 + tx*TN + 2*i;
            if (gc0 < N){
                float v = __uint_as_float(lo);
                if (bias) v += bias[gc0];
                if (ACT) v = tanhf(v);
                C[(size_t)gr*N + gc0] = v;
            }
            if (gc0+1 < N){
                float v = __uint_as_float(hi);
                if (bias) v += bias[gc0+1];
                if (ACT) v = tanhf(v);
                C[(size_t)gr*N + gc0+1] = v;
            }
        }
    }
}

// ---------------- persistent LSTM v2: 2 cols/thread, halved LDS ----------------
// grid (64,2)=128 blocks, 256 threads. thread=(sp 0..15, cgid 0..15):
// cols cgid*2..+1, K range sp*32..+31, all 16 batches. Weights in 64 regs.
__global__ void __launch_bounds__(256) k_lstm_all(const int* __restrict__ lengths){
    int ch = blockIdx.x, dir = blockIdx.y;
    __shared__ __align__(16) float buf[16*32*18];  // 36 KB; hsT uses stride-16, red stride-18
    int tid = threadIdx.x;
    int cgid = tid & 15, sp = tid >> 4;

    float w0[32], w1[32];
    {
        const float* wp = d_whP + (size_t)dir*H_*G4_ + (size_t)(sp*32)*G4_ + ch*32 + cgid*2;
        #pragma unroll
        for (int k = 0; k < 32; k++){
            float2 ww = *reinterpret_cast<const float2*>(&wp[(size_t)k*G4_]);
            w0[k] = ww.x; w1[k] = ww.y;
        }
    }
    int hl = tid >> 4, bb = tid & 15;              // combine mapping (tid<128)
    int lenb = (tid < 128) ? lengths[bb] : 0;
    int hg = ch*8 + hl;

    for (int t = 0; t < T_; t++){
        const float* hprev = d_hstate + dir*(B_*H_);
        for (int i = tid; i < H_*16; i += 256){
            int k = i >> 4, b = i & 15;
            buf[i] = hprev[b*H_ + k];
        }
        __syncthreads();

        unsigned long long a0[8] = {0,0,0,0,0,0,0,0};
        unsigned long long a1[8] = {0,0,0,0,0,0,0,0};
        const unsigned long long* hbase = reinterpret_cast<const unsigned long long*>(&buf[(sp*32)*16]);
        #pragma unroll
        for (int k = 0; k < 32; k++){
            unsigned long long wA, wB;
            asm("mov.b64 %0, {%1, %1};" : "=l"(wA) : "r"(__float_as_uint(w0[k])));
            asm("mov.b64 %0, {%1, %1};" : "=l"(wB) : "r"(__float_as_uint(w1[k])));
            const unsigned long long* hv = hbase + k*8;
            #pragma unroll
            for (int j=0;j<8;j++){
                unsigned long long h = hv[j];
                asm("fma.rn.f32x2 %0, %1, %2, %0;" : "+l"(a0[j]) : "l"(h), "l"(wA));
                asm("fma.rn.f32x2 %0, %1, %2, %0;" : "+l"(a1[j]) : "l"(h), "l"(wB));
            }
        }
        __syncthreads();                           // hsT reads done — alias as red (stride 18)
        {
            float* r0 = &buf[(sp*32 + cgid*2    )*18];
            float* r1 = &buf[(sp*32 + cgid*2 + 1)*18];
            #pragma unroll
            for (int j=0;j<8;j++){
                unsigned lo,hi;
                asm("mov.b64 {%0, %1}, %2;" : "=r"(lo), "=r"(hi) : "l"(a0[j]));
                r0[2*j] = __uint_as_float(lo); r0[2*j+1] = __uint_as_float(hi);
                asm("mov.b64 {%0, %1}, %2;" : "=r"(lo), "=r"(hi) : "l"(a1[j]));
                r1[2*j] = __uint_as_float(lo); r1[2*j+1] = __uint_as_float(hi);
            }
        }
        __syncthreads();

        if (tid < 128){
            const float* gpre = (dir ? d_gpre_bw : d_gpre_fw) + (size_t)(bb*T_ + t)*G4_;
            float g4[4];
            #pragma unroll
            for (int g = 0; g < 4; g++){
                int cc = hl*4 + g;
                float s = 0.f;
                #pragma unroll
                for (int q = 0; q < 16; q++) s += buf[(q*32 + cc)*18 + bb];
                g4[g] = s + gpre[g*H_ + hg];
            }
            int idx = (dir*B_ + bb)*H_ + hg;
            float cs = d_cstate[idx], hp = d_hstate[idx];
            float cn = sigmf(g4[2] + 1.f)*cs + sigmf(g4[0])*tanhf(g4[1]);
            float hn = sigmf(g4[3])*tanhf(cn);
            bool m = (t < lenb);
            d_cstate[idx] = m ? cn : cs;
            d_hstate[idx] = m ? hn : hp;
            float ho = m ? hn : 0.f;
            if (dir == 0) d_hcat[(size_t)(bb*T_ + t)*(2*H_) + hg] = ho;
            else { int p = m ? (lenb-1-t) : t; d_hcat[(size_t)(bb*T_ + p)*(2*H_) + H_ + hg] = ho; }
        }

        __threadfence();
        __syncthreads();
        if (tid == 0){
            atomicAdd(&d_bars[t], 1u);
            while (*((volatile unsigned*)&d_bars[t]) < 128u) {}
        }
        __syncthreads();
        __threadfence();
    }
}

// single-pass online softmax row reduce over 32000 logits
__global__ void k_rowreduce(){
    int row = blockIdx.x, tid = threadIdx.x;
    const float4* p = reinterpret_cast<const float4*>(d_logits + (size_t)row*VS_);
    float m = -1e30f, s = 0.f;
    for (int v = tid; v < VS_/4; v += 256){
        float4 x = p[v];
        #pragma unroll
        for (int q = 0; q < 4; q++){
            float xv = (q==0)?x.x:(q==1)?x.y:(q==2)?x.z:x.w;
            if (xv > m){ s = s*expf(m - xv) + 1.f; m = xv; }
            else        s += expf(xv - m);
        }
    }
    __shared__ float sm[256], ss[256];
    sm[tid] = m; ss[tid] = s; __syncthreads();
    for (int st = 128; st > 0; st >>= 1){
        if (tid < st){
            float m1 = sm[tid], m2 = sm[tid+st];
            float mm = fmaxf(m1, m2);
            ss[tid] = ss[tid]*expf(m1-mm) + ss[tid+st]*expf(m2-mm);
            sm[tid] = mm;
        }
        __syncthreads();
    }
    if (tid == 0){ d_rowmax[row] = sm[0]; d_rowsum[row] = ss[0]; }
}

__global__ void k_nulllogits(const float* __restrict__ Wv, const float* __restrict__ bv){
    __shared__ float ns[H_];
    int tid = threadIdx.x;
    for (int k=tid; k<H_; k+=256) ns[k] = d_nullstate[k];
    __syncthreads();
    int v = blockIdx.x*256 + tid;
    if (v < VS_){
        float a = bv[v];
        #pragma unroll 4
        for (int k=0;k<H_;k++) a = fmaf(ns[k], Wv[(size_t)k*VS_+v], a);
        d_nulllog[v] = a;
    }
}

__global__ void k_nullreduce(){
    __shared__ float sm[1024];
    int tid = threadIdx.x;
    float m = -1e30f;
    for (int v=tid; v<VS_; v+=1024) m = fmaxf(m, d_nulllog[v]);
    sm[tid]=m; __syncthreads();
    for (int s=512;s>0;s>>=1){ if(tid<s) sm[tid]=fmaxf(sm[tid],sm[tid+s]); __syncthreads(); }
    float mx = sm[0]; __syncthreads();
    float su = 0.f;
    for (int v=tid; v<VS_; v+=1024) su += expf(d_nulllog[v]-mx);
    sm[tid]=su; __syncthreads();
    for (int s=512;s>0;s>>=1){ if(tid<s) sm[tid]+=sm[tid+s]; __syncthreads(); }
    if (tid==0){ d_nullred[0]=mx; d_nullred[1]=sm[0]; }
}

__global__ void k_emission(const int* __restrict__ sources, float* __restrict__ out){
    int bt = blockIdx.x, b = bt>>6, t = bt&63, s = threadIdx.x;   // 64
    int col = sources[b*S_+s];
    float l = d_logits[(size_t)bt*VS_ + col];
    out[(size_t)b*(2*T_*S_) + t*S_ + s] = expf(l - d_rowmax[bt]) / d_rowsum[bt];
    out[(size_t)b*(2*T_*S_) + (T_+t)*S_ + s] = expf(d_nulllog[col]-d_nullred[0]) / d_nullred[1];
}

__global__ void k_jsoftmax(){
    int row = blockIdx.x, tid = threadIdx.x;
    float* p = d_jl + (size_t)row*J_;
    __shared__ float sm[256];
    float m = -1e30f;
    for (int j=tid; j<J_; j+=256) m = fmaxf(m, p[j]);
    sm[tid]=m; __syncthreads();
    for (int s=128;s>0;s>>=1){ if(tid<s) sm[tid]=fmaxf(sm[tid],sm[tid+s]); __syncthreads(); }
    float mx = sm[0]; __syncthreads();
    float su = 0.f;
    for (int j=tid; j<J_; j+=256) su += expf(p[j]-mx);
    sm[tid]=su; __syncthreads();
    for (int s=128;s>0;s>>=1){ if(tid<s) sm[tid]+=sm[tid+s]; __syncthreads(); }
    float inv = 1.f/sm[0]; __syncthreads();
    for (int j=tid; j<J_; j+=256) p[j] = expf(p[j]-mx)*inv;
}

__global__ void k_p0(const float* __restrict__ Wp0, const float* __restrict__ bp0){
    int gw = (blockIdx.x*blockDim.x + threadIdx.x) >> 5;
    int lane = threadIdx.x & 31;
    if (gw >= BT_) return;
    float a = 0.f;
    for (int k=lane; k<H_; k+=32) a = fmaf(d_tt[(size_t)gw*H_+k], Wp0[k], a);
    #pragma unroll
    for (int o=16;o>0;o>>=1) a += __shfl_xor_sync(0xffffffffu, a, o);
    if (lane==0) d_p0v[gw] = sigmf(a + bp0[0]);
}

__global__ void k_transition(float* __restrict__ out){
    int b = blockIdx.y;
    int idx = blockIdx.x*256 + threadIdx.x;
    if (idx >= T_*2*T_) return;
    int i = idx / (2*T_), c = idx % (2*T_);
    float tv, lv;
    if (c < T_){
        float jw = d_jl[(size_t)(b*T_+i)*J_ + (MM_ + c - i)];
        tv = jw; lv = logf(jw);
    } else {
        int j = c - T_;
        float p = d_p0v[b*T_+i];
        tv = (i==j) ? p : 0.f;
        lv = (i==j) ? logf(p) : 0.f;
    }
    float* tr  = out + (size_t)B_*2*T_*S_ + (size_t)b*(2*T_*2*T_);
    float* trl = tr + (size_t)B_*2*T_*2*T_;
    tr [i*2*T_ + c] = tv;  tr [(T_+i)*2*T_ + c] = tv;
    trl[i*2*T_ + c] = lv;  trl[(T_+i)*2*T_ + c] = lv;
}

extern "C" void kernel_launch(void* const* d_in, const int* in_sizes, int n_in,
                              void* d_out, int out_size) {
    const int*   sources = (const int*)  d_in[0];
    const int*   targets = (const int*)  d_in[1];
    const int*   tnull   = (const int*)  d_in[2];
    const int*   lengths = (const int*)  d_in[3];
    const float* emb     = (const float*)d_in[4];
    const float* nnW     = (const float*)d_in[5];
    const float* nnb     = (const float*)d_in[6];
    const float* Wx_fw   = (const float*)d_in[7];
    const float* Wh_fw   = (const float*)d_in[8];
    const float* b_fw    = (const float*)d_in[9];
    const float* Wx_bw   = (const float*)d_in[10];
    const float* Wh_bw   = (const float*)d_in[11];
    const float* b_bw    = (const float*)d_in[12];
    const float* Wproj_e = (const float*)d_in[13];
    const float* Wv      = (const float*)d_in[14];
    const float* bv      = (const float*)d_in[15];
    const float* Wproj_t = (const float*)d_in[16];
    const float* Wj      = (const float*)d_in[17];
    const float* bj      = (const float*)d_in[18];
    const float* Wp0     = (const float*)d_in[19];
    const float* bp0     = (const float*)d_in[20];
    float* out = (float*)d_out;

    float *gfw, *gbw, *xp, *xrp, *hc, *lg, *tmp, *ttp, *jl;
    __nv_bfloat16 *tsb, *wvT;
    cudaGetSymbolAddress((void**)&gfw, d_gpre_fw);
    cudaGetSymbolAddress((void**)&gbw, d_gpre_bw);
    cudaGetSymbolAddress((void**)&xp,  d_x);
    cudaGetSymbolAddress((void**)&xrp, d_xrev);
    cudaGetSymbolAddress((void**)&hc,  d_hcat);
    cudaGetSymbolAddress((void**)&lg,  d_logits);
    cudaGetSymbolAddress((void**)&tmp, d_tmpt);
    cudaGetSymbolAddress((void**)&ttp, d_tt);
    cudaGetSymbolAddress((void**)&jl,  d_jl);
    cudaGetSymbolAddress((void**)&tsb, d_tsb);
    cudaGetSymbolAddress((void**)&wvT, d_wvT);

    k_init<<<64,256>>>();
    k_embed<<<BT_,256>>>(targets, lengths, emb);
    k_nullstate<<<1,512>>>(tnull, emb, nnW, nnb);
    k_permwh<<<512,256>>>(Wh_fw, Wh_bw);
    k_cvt_wvT<<<dim3(1000,16),dim3(32,8)>>>(Wv);

    // input projections (tf32, standard gate layout)
    tf32gemm_k<0><<<dim3(8,16),256>>>(xp,  Wx_fw, b_fw, gfw, BT_, G4_, E_);
    tf32gemm_k<0><<<dim3(8,16),256>>>(xrp, Wx_bw, b_bw, gbw, BT_, G4_, E_);

    // persistent LSTM (all 64 timesteps, internal grid barriers)
    k_lstm_all<<<dim3(64,2),256>>>(lengths);

    // emission path
    tf32gemm_bf16o_k<<<dim3(8,4),256>>>(hc, Wproj_e, tsb, BT_, H_, 2*H_);
    bf16gemm_k<512><<<dim3(8,250),256>>>(tsb, wvT, bv, lg, BT_, VS_);
    k_rowreduce<<<BT_,256>>>();
    k_nulllogits<<<125,256>>>(Wv, bv);
    k_nullreduce<<<1,1024>>>();
    k_emission<<<BT_,64>>>(sources, out);

    // transition path (tf32 for the two big ones, sgemm for N=201)
    tf32gemm_k<0><<<dim3(8,2),256>>>(hc, Wproj_t, nullptr, tmp, BT_, E_, 2*H_);
    tf32gemm_k<1><<<dim3(8,4),256>>>(tmp, nnW, nnb, ttp, BT_, H_, E_);
    sgemm_k<0><<<dim3(2,16),256>>>(ttp, Wj, bj, jl, BT_, J_, H_);
    k_jsoftmax<<<BT_,256>>>();
    k_p0<<<128,256>>>(Wp0, bp0);
    k_transition<<<dim3(32,16),256>>>(out);
}

// round 15
// speedup vs baseline: 1.8951x; 1.0183x over previous
#include <cuda_runtime.h>
#include <cuda_bf16.h>
#include <cstdint>

#define B_  16
#define S_  64
#define T_  64
#define E_  256
#define H_  512
#define VS_ 32000
#define MM_ 100
#define J_  201
#define BT_ (B_*T_)
#define G4_ (4*H_)
#define NCT_ (VS_/128)   // 250 col tiles

__device__ float d_x[BT_*E_];
__device__ float d_xrev[BT_*E_];
__device__ float d_gpre_fw[BT_*G4_];
__device__ float d_gpre_bw[BT_*G4_];
__device__ float d_hstate[2*B_*H_];
__device__ float d_cstate[2*B_*H_];
__device__ float d_hcat[BT_*2*H_];
__device__ float d_rowmax[BT_];
__device__ float d_rowsum[BT_];
__device__ float d_nullstate[H_];
__device__ float d_nulllog[VS_];
__device__ float d_nullred[2];
__device__ float d_tmpt[BT_*E_];
__device__ float d_tt[BT_*H_];
__device__ float d_jl[BT_*J_];
__device__ float d_p0v[BT_];
__device__ __nv_bfloat16 d_tsb[BT_*H_];
__device__ __nv_bfloat16 d_wvT[(size_t)VS_*H_];
__device__ float d_whP[2*H_*G4_];
__device__ unsigned d_bars[T_];
__device__ int   d_colmap[(size_t)B_*VS_];
__device__ float d_glog[BT_*S_];
__device__ float d_pmax[(size_t)BT_*NCT_];
__device__ float d_psum[(size_t)BT_*NCT_];

__device__ __forceinline__ float sigmf(float x){ return 1.f/(1.f+expf(-x)); }
__device__ __forceinline__ uint32_t f2tf32(float v){
    uint32_t r; asm("cvt.rna.tf32.f32 %0, %1;" : "=r"(r) : "f"(v)); return r;
}

__global__ void k_init(){
    int i = blockIdx.x*blockDim.x + threadIdx.x;
    if (i < 2*B_*H_){ d_hstate[i]=0.f; d_cstate[i]=0.f; }
    if (i < T_) d_bars[i] = 0u;
}

__global__ void k_srcmap_clear(){
    int i = blockIdx.x*blockDim.x + threadIdx.x;
    if (i < B_*VS_) d_colmap[i] = -1;
}
__global__ void k_srcmap_fill(const int* __restrict__ sources){
    int i = blockIdx.x*blockDim.x + threadIdx.x;   // over B_*S_ = 1024
    if (i < B_*S_){
        int b = i >> 6, s = i & 63;
        d_colmap[(size_t)b*VS_ + sources[i]] = s;
    }
}

__global__ void k_embed(const int* __restrict__ targets, const int* __restrict__ lengths,
                        const float* __restrict__ emb){
    int bt = blockIdx.x, b = bt/T_, t = bt%T_;
    int len = lengths[b];
    int rt = (t < len) ? (len-1-t) : t;
    int r0 = targets[bt], r1 = targets[b*T_+rt];
    for (int e = threadIdx.x; e < E_; e += blockDim.x){
        d_x[bt*E_+e]    = emb[(size_t)r0*E_+e];
        d_xrev[bt*E_+e] = emb[(size_t)r1*E_+e];
    }
}

__global__ void k_nullstate(const int* __restrict__ tnull, const float* __restrict__ emb,
                            const float* __restrict__ nnW, const float* __restrict__ nnb){
    __shared__ float xe[E_];
    int tid = threadIdx.x;          // 512
    int r = tnull[0];
    for (int e = tid; e < E_; e += blockDim.x) xe[e] = emb[(size_t)r*E_+e];
    __syncthreads();
    float a = nnb[tid];
    #pragma unroll 4
    for (int e = 0; e < E_; e++) a = fmaf(xe[e], nnW[e*H_+tid], a);
    d_nullstate[tid] = tanhf(a);
}

__global__ void k_permwh(const float* __restrict__ Whf, const float* __restrict__ Whb){
    int stride = gridDim.x*blockDim.x;
    for (int i = blockIdx.x*blockDim.x + threadIdx.x; i < 2*H_*G4_; i += stride){
        int dir = i / (H_*G4_); int r = (i >> 11) & (H_-1); int c = i & (G4_-1);
        int g = c & 3, h = c >> 2;
        d_whP[i] = (dir ? Whb : Whf)[(size_t)r*G4_ + g*H_ + h];
    }
}

__global__ void k_cvt_wvT(const float* __restrict__ Wv){
    __shared__ float tile[32][33];
    int nb = blockIdx.x, kb = blockIdx.y;
    int tx = threadIdx.x, ty = threadIdx.y;   // 32 x 8
    #pragma unroll
    for (int i = 0; i < 32; i += 8)
        tile[ty+i][tx] = Wv[(size_t)(kb*32+ty+i)*VS_ + nb*32+tx];
    __syncthreads();
    #pragma unroll
    for (int i = 0; i < 32; i += 8)
        d_wvT[(size_t)(nb*32+ty+i)*H_ + kb*32+tx] = __float2bfloat16(tile[tx][ty+i]);
}

#define CP_ASYNC16(dst, src) \
    asm volatile("cp.async.cg.shared.global [%0], [%1], 16;\n" :: "r"(dst), "l"(src))
#define CP_COMMIT() asm volatile("cp.async.commit_group;\n" ::: "memory")
#define CP_WAIT(n)  asm volatile("cp.async.wait_group %0;\n" :: "n"(n) : "memory")

// ---------------- bf16 logits GEMM with fused softmax partials + source gather ----------------
// grid=(M/128, NCT_), 256 thr. A[M,512]bf16, BT[VS,512]bf16. No logits store:
// writes gathered cols to d_glog and per-(row,tile) online-softmax partials.
__global__ void __launch_bounds__(256) bf16gemm_fused_k(const __nv_bfloat16* __restrict__ A,
                                                        const __nv_bfloat16* __restrict__ BT,
                                                        const float* __restrict__ bias)
{
    const int KV = 512, BK = 32, LDW = 40, NCH = KV/BK;
    __shared__ __align__(16) __nv_bfloat16 As[2][128*LDW];
    __shared__ __align__(16) __nv_bfloat16 Bs[2][128*LDW];
    __shared__ float sred[4][2][2][8][2][2];   // [wm][mt][ab][gid][wn][max/sum]
    int tid = threadIdx.x, lane = tid & 31, wid = tid >> 5;
    int wm = wid & 3, wn = wid >> 2;
    int gid = lane >> 2, tig = lane & 3;
    int row0 = blockIdx.x * 128, col0 = blockIdx.y * 128;
    uint32_t sA = (uint32_t)__cvta_generic_to_shared(&As[0][0]);
    uint32_t sB = (uint32_t)__cvta_generic_to_shared(&Bs[0][0]);
    const uint32_t STG = 128*LDW*2;

    int r0s = (tid*2) >> 2, q0 = ((tid*2) & 3)*8;
    int r1s = (tid*2+1) >> 2, q1 = ((tid*2+1) & 3)*8;
    const __nv_bfloat16* ga0 = A + (size_t)(row0 + r0s)*KV + q0;
    const __nv_bfloat16* ga1 = A + (size_t)(row0 + r1s)*KV + q1;
    const __nv_bfloat16* gb0 = BT + (size_t)(col0 + r0s)*KV + q0;
    const __nv_bfloat16* gb1 = BT + (size_t)(col0 + r1s)*KV + q1;
    uint32_t a0d = (uint32_t)(r0s*LDW + q0)*2, a1d = (uint32_t)(r1s*LDW + q1)*2;

    float c[2][8][4];
    #pragma unroll
    for (int mt=0; mt<2; mt++){
        #pragma unroll
        for (int nt=0; nt<8; nt++){
            #pragma unroll
            for (int q=0; q<4; q++) c[mt][nt][q] = 0.f;
        }
    }

    CP_ASYNC16(sA + a0d, ga0);
    CP_ASYNC16(sA + a1d, ga1);
    CP_ASYNC16(sB + a0d, gb0);
    CP_ASYNC16(sB + a1d, gb1);
    CP_COMMIT();
    int lq = lane >> 3, lr = lane & 7;

    #pragma unroll
    for (int kc = 0; kc < NCH; kc++){
        int cur = kc & 1;
        if (kc + 1 < NCH){
            int nxt = (kc+1) & 1;
            int k0 = (kc+1)*BK;
            CP_ASYNC16(sA + nxt*STG + a0d, ga0 + k0);
            CP_ASYNC16(sA + nxt*STG + a1d, ga1 + k0);
            CP_ASYNC16(sB + nxt*STG + a0d, gb0 + k0);
            CP_ASYNC16(sB + nxt*STG + a1d, gb1 + k0);
            CP_COMMIT();
            CP_WAIT(1);
        } else {
            CP_WAIT(0);
        }
        __syncthreads();
        uint32_t baseA = sA + cur*STG, baseB = sB + cur*STG;
        #pragma unroll
        for (int kk = 0; kk < BK; kk += 16){
            uint32_t a[2][4], b[8][2];
            #pragma unroll
            for (int mt=0; mt<2; mt++){
                int row = wm*32 + mt*16 + (lq&1)*8 + lr;
                int col = kk + (lq>>1)*8;
                uint32_t addr = baseA + (uint32_t)(row*LDW + col)*2;
                asm volatile("ldmatrix.sync.aligned.m8n8.x4.shared.b16 {%0,%1,%2,%3}, [%4];"
                    : "=r"(a[mt][0]), "=r"(a[mt][1]), "=r"(a[mt][2]), "=r"(a[mt][3]) : "r"(addr));
            }
            #pragma unroll
            for (int p=0; p<4; p++){
                int row = wn*64 + p*16 + (lq&1)*8 + lr;
                int col = kk + (lq>>1)*8;
                uint32_t addr = baseB + (uint32_t)(row*LDW + col)*2;
                asm volatile("ldmatrix.sync.aligned.m8n8.x4.shared.b16 {%0,%1,%2,%3}, [%4];"
                    : "=r"(b[2*p][0]), "=r"(b[2*p+1][0]), "=r"(b[2*p][1]), "=r"(b[2*p+1][1]) : "r"(addr));
            }
            #pragma unroll
            for (int mt=0; mt<2; mt++){
                #pragma unroll
                for (int nt=0; nt<8; nt++)
                    asm("mma.sync.aligned.m16n8k16.row.col.f32.bf16.bf16.f32 "
                        "{%0,%1,%2,%3}, {%4,%5,%6,%7}, {%8,%9}, {%0,%1,%2,%3};"
                        : "+f"(c[mt][nt][0]), "+f"(c[mt][nt][1]),
                          "+f"(c[mt][nt][2]), "+f"(c[mt][nt][3])
                        : "r"(a[mt][0]), "r"(a[mt][1]), "r"(a[mt][2]), "r"(a[mt][3]),
                          "r"(b[nt][0]), "r"(b[nt][1]));
            }
        }
        __syncthreads();
    }

    // fused epilogue: bias, gather, per-row online-softmax partials (no logits store)
    #pragma unroll
    for (int mt=0; mt<2; mt++){
        int rA = row0 + wm*32 + mt*16 + gid;      // rB = rA+8 same batch (16-aligned blocks)
        const int* cmap = d_colmap + (size_t)(rA >> 6)*VS_;
        float mxA = -1e30f, mxB = -1e30f, sAc = 0.f, sBc = 0.f;
        #pragma unroll
        for (int nt=0; nt<8; nt++){
            int cc = col0 + wn*64 + nt*8 + tig*2;
            float b0 = bias[cc], b1 = bias[cc+1];
            float vA0 = c[mt][nt][0] + b0, vA1 = c[mt][nt][1] + b1;
            float vB0 = c[mt][nt][2] + b0, vB1 = c[mt][nt][3] + b1;
            int m0 = cmap[cc], m1 = cmap[cc+1];
            if (m0 >= 0){ d_glog[rA*S_+m0] = vA0; d_glog[(rA+8)*S_+m0] = vB0; }
            if (m1 >= 0){ d_glog[rA*S_+m1] = vA1; d_glog[(rA+8)*S_+m1] = vB1; }
            // online merge 2 values each
            float m2 = fmaxf(vA0, vA1);
            float s2 = expf(vA0-m2) + expf(vA1-m2);
            float mm = fmaxf(mxA, m2);
            sAc = sAc*expf(mxA-mm) + s2*expf(m2-mm); mxA = mm;
            m2 = fmaxf(vB0, vB1);
            s2 = expf(vB0-m2) + expf(vB1-m2);
            mm = fmaxf(mxB, m2);
            sBc = sBc*expf(mxB-mm) + s2*expf(m2-mm); mxB = mm;
        }
        #pragma unroll
        for (int o = 1; o <= 2; o <<= 1){
            float mo = __shfl_xor_sync(0xffffffffu, mxA, o);
            float so = __shfl_xor_sync(0xffffffffu, sAc, o);
            float mm = fmaxf(mxA, mo);
            sAc = sAc*expf(mxA-mm) + so*expf(mo-mm); mxA = mm;
            mo = __shfl_xor_sync(0xffffffffu, mxB, o);
            so = __shfl_xor_sync(0xffffffffu, sBc, o);
            mm = fmaxf(mxB, mo);
            sBc = sBc*expf(mxB-mm) + so*expf(mo-mm); mxB = mm;
        }
        if (tig == 0){
            sred[wm][mt][0][gid][wn][0] = mxA; sred[wm][mt][0][gid][wn][1] = sAc;
            sred[wm][mt][1][gid][wn][0] = mxB; sred[wm][mt][1][gid][wn][1] = sBc;
        }
    }
    __syncthreads();
    if (tid < 128){
        int wmI = tid >> 5, mtI = (tid >> 4) & 1, abI = (tid >> 3) & 1, gI = tid & 7;
        float m0 = sred[wmI][mtI][abI][gI][0][0], s0 = sred[wmI][mtI][abI][gI][0][1];
        float m1 = sred[wmI][mtI][abI][gI][1][0], s1 = sred[wmI][mtI][abI][gI][1][1];
        float mm = fmaxf(m0, m1);
        float ss = s0*expf(m0-mm) + s1*expf(m1-mm);
        int row = row0 + wmI*32 + mtI*16 + abI*8 + gI;
        d_pmax[(size_t)row*NCT_ + blockIdx.y] = mm;
        d_psum[(size_t)row*NCT_ + blockIdx.y] = ss;
    }
}

// final per-row merge of NCT_ partials
__global__ void k_rowfinal(){
    int row = blockIdx.x, tid = threadIdx.x;     // 256 threads
    float m = -1e30f, s = 0.f;
    if (tid < NCT_){
        m = d_pmax[(size_t)row*NCT_ + tid];
        s = d_psum[(size_t)row*NCT_ + tid];
    }
    __shared__ float sm[256], ss[256];
    sm[tid] = m; ss[tid] = s; __syncthreads();
    for (int st = 128; st > 0; st >>= 1){
        if (tid < st){
            float m1 = sm[tid], m2 = sm[tid+st];
            float mm = fmaxf(m1, m2);
            ss[tid] = ss[tid]*expf(m1-mm) + ss[tid+st]*expf(m2-mm);
            sm[tid] = mm;
        }
        __syncthreads();
    }
    if (tid == 0){ d_rowmax[row] = sm[0]; d_rowsum[row] = ss[0]; }
}

// ---------------- tf32 mma.sync GEMM, fp32 out + bias (+tanh if ACT) ----------------
template<int ACT>
__global__ void tf32gemm_k(const float* __restrict__ A, const float* __restrict__ Bm,
                           const float* __restrict__ bias, float* __restrict__ C,
                           int M, int N, int K)
{
    __shared__ float As[16][132];
    __shared__ float Bs[16][132];
    int tid = threadIdx.x, lane = tid & 31, wid = tid >> 5;
    int wm = wid & 3, wn = wid >> 2;
    int gid = lane >> 2, tig = lane & 3;
    int row0 = blockIdx.x * 128, col0 = blockIdx.y * 128;

    float c[2][8][4];
    #pragma unroll
    for (int mt=0; mt<2; mt++){
        #pragma unroll
        for (int nt=0; nt<8; nt++){
            #pragma unroll
            for (int q=0; q<4; q++) c[mt][nt][q] = 0.f;
        }
    }

    for (int k0 = 0; k0 < K; k0 += 16){
        #pragma unroll
        for (int j = 0; j < 2; j++){
            int s = tid*2 + j;
            int r = s >> 2, kq = (s & 3)*4;
            float4 v = *reinterpret_cast<const float4*>(&A[(size_t)(row0 + r)*K + k0 + kq]);
            As[kq+0][r] = __uint_as_float(f2tf32(v.x));
            As[kq+1][r] = __uint_as_float(f2tf32(v.y));
            As[kq+2][r] = __uint_as_float(f2tf32(v.z));
            As[kq+3][r] = __uint_as_float(f2tf32(v.w));
        }
        #pragma unroll
        for (int j = 0; j < 2; j++){
            int s = tid*2 + j;
            int r = s >> 5, c4 = (s & 31)*4;
            float4 v = *reinterpret_cast<const float4*>(&Bm[(size_t)(k0 + r)*N + col0 + c4]);
            Bs[r][c4+0] = __uint_as_float(f2tf32(v.x));
            Bs[r][c4+1] = __uint_as_float(f2tf32(v.y));
            Bs[r][c4+2] = __uint_as_float(f2tf32(v.z));
            Bs[r][c4+3] = __uint_as_float(f2tf32(v.w));
        }
        __syncthreads();
        #pragma unroll
        for (int kk = 0; kk < 2; kk++){
            int kb = kk*8;
            uint32_t a[2][4], b[8][2];
            #pragma unroll
            for (int mt=0; mt<2; mt++){
                int r = wm*32 + mt*16 + gid;
                a[mt][0] = __float_as_uint(As[kb+tig  ][r  ]);
                a[mt][1] = __float_as_uint(As[kb+tig  ][r+8]);
                a[mt][2] = __float_as_uint(As[kb+tig+4][r  ]);
                a[mt][3] = __float_as_uint(As[kb+tig+4][r+8]);
            }
            #pragma unroll
            for (int nt=0; nt<8; nt++){
                int n = wn*64 + nt*8 + gid;
                b[nt][0] = __float_as_uint(Bs[kb+tig  ][n]);
                b[nt][1] = __float_as_uint(Bs[kb+tig+4][n]);
            }
            #pragma unroll
            for (int mt=0; mt<2; mt++){
                #pragma unroll
                for (int nt=0; nt<8; nt++)
                    asm("mma.sync.aligned.m16n8k8.row.col.f32.tf32.tf32.f32 "
                        "{%0,%1,%2,%3}, {%4,%5,%6,%7}, {%8,%9}, {%0,%1,%2,%3};"
                        : "+f"(c[mt][nt][0]), "+f"(c[mt][nt][1]),
                          "+f"(c[mt][nt][2]), "+f"(c[mt][nt][3])
                        : "r"(a[mt][0]), "r"(a[mt][1]), "r"(a[mt][2]), "r"(a[mt][3]),
                          "r"(b[nt][0]), "r"(b[nt][1]));
            }
        }
        __syncthreads();
    }
    #pragma unroll
    for (int mt=0; mt<2; mt++){
        int r = row0 + wm*32 + mt*16 + gid;
        #pragma unroll
        for (int nt=0; nt<8; nt++){
            int cc = col0 + wn*64 + nt*8 + tig*2;
            float b0 = bias ? bias[cc] : 0.f;
            float b1 = bias ? bias[cc+1] : 0.f;
            float v0 = c[mt][nt][0] + b0, v1 = c[mt][nt][1] + b1;
            float v2 = c[mt][nt][2] + b0, v3 = c[mt][nt][3] + b1;
            if (ACT){ v0=tanhf(v0); v1=tanhf(v1); v2=tanhf(v2); v3=tanhf(v3); }
            C[(size_t)r*N + cc]       = v0;
            C[(size_t)r*N + cc + 1]   = v1;
            C[(size_t)(r+8)*N + cc]   = v2;
            C[(size_t)(r+8)*N + cc+1] = v3;
        }
    }
}

// ---------------- tf32 mma.sync GEMM, bf16 output (proj_e) ----------------
__global__ void tf32gemm_bf16o_k(const float* __restrict__ A, const float* __restrict__ Bm,
                                 __nv_bfloat16* __restrict__ Cb, int M, int N, int K)
{
    __shared__ float As[16][132];
    __shared__ float Bs[16][132];
    int tid = threadIdx.x, lane = tid & 31, wid = tid >> 5;
    int wm = wid & 3, wn = wid >> 2;
    int gid = lane >> 2, tig = lane & 3;
    int row0 = blockIdx.x * 128, col0 = blockIdx.y * 128;

    float c[2][8][4];
    #pragma unroll
    for (int mt=0; mt<2; mt++){
        #pragma unroll
        for (int nt=0; nt<8; nt++){
            #pragma unroll
            for (int q=0; q<4; q++) c[mt][nt][q] = 0.f;
        }
    }

    for (int k0 = 0; k0 < K; k0 += 16){
        #pragma unroll
        for (int j = 0; j < 2; j++){
            int s = tid*2 + j;
            int r = s >> 2, kq = (s & 3)*4;
            float4 v = *reinterpret_cast<const float4*>(&A[(size_t)(row0 + r)*K + k0 + kq]);
            As[kq+0][r] = __uint_as_float(f2tf32(v.x));
            As[kq+1][r] = __uint_as_float(f2tf32(v.y));
            As[kq+2][r] = __uint_as_float(f2tf32(v.z));
            As[kq+3][r] = __uint_as_float(f2tf32(v.w));
        }
        #pragma unroll
        for (int j = 0; j < 2; j++){
            int s = tid*2 + j;
            int r = s >> 5, c4 = (s & 31)*4;
            float4 v = *reinterpret_cast<const float4*>(&Bm[(size_t)(k0 + r)*N + col0 + c4]);
            Bs[r][c4+0] = __uint_as_float(f2tf32(v.x));
            Bs[r][c4+1] = __uint_as_float(f2tf32(v.y));
            Bs[r][c4+2] = __uint_as_float(f2tf32(v.z));
            Bs[r][c4+3] = __uint_as_float(f2tf32(v.w));
        }
        __syncthreads();
        #pragma unroll
        for (int kk = 0; kk < 2; kk++){
            int kb = kk*8;
            uint32_t a[2][4], b[8][2];
            #pragma unroll
            for (int mt=0; mt<2; mt++){
                int r = wm*32 + mt*16 + gid;
                a[mt][0] = __float_as_uint(As[kb+tig  ][r  ]);
                a[mt][1] = __float_as_uint(As[kb+tig  ][r+8]);
                a[mt][2] = __float_as_uint(As[kb+tig+4][r  ]);
                a[mt][3] = __float_as_uint(As[kb+tig+4][r+8]);
            }
            #pragma unroll
            for (int nt=0; nt<8; nt++){
                int n = wn*64 + nt*8 + gid;
                b[nt][0] = __float_as_uint(Bs[kb+tig  ][n]);
                b[nt][1] = __float_as_uint(Bs[kb+tig+4][n]);
            }
            #pragma unroll
            for (int mt=0; mt<2; mt++){
                #pragma unroll
                for (int nt=0; nt<8; nt++)
                    asm("mma.sync.aligned.m16n8k8.row.col.f32.tf32.tf32.f32 "
                        "{%0,%1,%2,%3}, {%4,%5,%6,%7}, {%8,%9}, {%0,%1,%2,%3};"
                        : "+f"(c[mt][nt][0]), "+f"(c[mt][nt][1]),
                          "+f"(c[mt][nt][2]), "+f"(c[mt][nt][3])
                        : "r"(a[mt][0]), "r"(a[mt][1]), "r"(a[mt][2]), "r"(a[mt][3]),
                          "r"(b[nt][0]), "r"(b[nt][1]));
            }
        }
        __syncthreads();
    }
    #pragma unroll
    for (int mt=0; mt<2; mt++){
        int r = row0 + wm*32 + mt*16 + gid;
        #pragma unroll
        for (int nt=0; nt<8; nt++){
            int cc = col0 + wn*64 + nt*8 + tig*2;
            Cb[(size_t)r*N + cc]       = __float2bfloat16(c[mt][nt][0]);
            Cb[(size_t)r*N + cc + 1]   = __float2bfloat16(c[mt][nt][1]);
            Cb[(size_t)(r+8)*N + cc]   = __float2bfloat16(c[mt][nt][2]);
            Cb[(size_t)(r+8)*N + cc+1] = __float2bfloat16(c[mt][nt][3]);
        }
    }
}

// tiled SGEMM, packed f32x2 FMA (N=201 GEMM)
template<int ACT>
__global__ void sgemm_k(const float* __restrict__ A, const float* __restrict__ Bm,
                        const float* __restrict__ bias, float* __restrict__ C,
                        int M, int N, int K)
{
    const int BM=64, BN=128, BK=16, TM=4, TN=8, THREADS=256;
    __shared__ float As[BM][BK+1];
    __shared__ __align__(16) float Bs[BK][BN];
    int tid = threadIdx.x;
    int tx = tid % (BN/TN), ty = tid / (BN/TN);
    int row0 = blockIdx.y*BM, col0 = blockIdx.x*BN;
    unsigned long long acc2[TM][TN/2];
    #pragma unroll
    for (int m=0;m<TM;m++){
        #pragma unroll
        for (int i=0;i<TN/2;i++) acc2[m][i]=0ull;
    }
    for (int k0 = 0; k0 < K; k0 += BK){
        for (int l = tid; l < BM*BK; l += THREADS){
            int r=l/BK, c=l%BK;
            As[r][c] = A[(size_t)(row0+r)*K + k0 + c];
        }
        for (int l = tid; l < BK*BN; l += THREADS){
            int r=l/BN, c=l%BN, gc=col0+c;
            Bs[r][c] = (gc<N) ? Bm[(size_t)(k0+r)*N + gc] : 0.f;
        }
        __syncthreads();
        #pragma unroll
        for (int kk=0; kk<BK; kk++){
            unsigned long long b2[TN/2];
            #pragma unroll
            for (int i=0;i<TN/2;i++)
                b2[i] = *reinterpret_cast<const unsigned long long*>(&Bs[kk][tx*TN+2*i]);
            #pragma unroll
            for (int m=0;m<TM;m++){
                float av = As[ty*TM+m][kk];
                unsigned long long a2;
                asm("mov.b64 %0, {%1, %1};" : "=l"(a2) : "r"(__float_as_uint(av)));
                #pragma unroll
                for (int i=0;i<TN/2;i++)
                    asm("fma.rn.f32x2 %0, %1, %2, %0;" : "+l"(acc2[m][i]) : "l"(a2), "l"(b2[i]));
            }
        }
        __syncthreads();
    }
    #pragma unroll
    for (int m=0;m<TM;m++){
        int gr = row0 + ty*TM + m;
        #pragma unroll
        for (int i=0;i<TN/2;i++){
            unsigned lo,hi;
            asm("mov.b64 {%0, %1}, %2;" : "=r"(lo), "=r"(hi) : "l"(acc2[m][i]));
            int gc0 = col0 + tx*TN + 2*i;
            if (gc0 < N){
                float v = __uint_as_float(lo);
                if (bias) v += bias[gc0];
                if (ACT) v = tanhf(v);
                C[(size_t)gr*N + gc0] = v;
            }
            if (gc0+1 < N){
                float v = __uint_as_float(hi);
                if (bias) v += bias[gc0+1];
                if (ACT) v = tanhf(v);
                C[(size_t)gr*N + gc0+1] = v;
            }
        }
    }
}

// ---------------- persistent LSTM v2 (R14, unchanged) ----------------
__global__ void __launch_bounds__(256) k_lstm_all(const int* __restrict__ lengths){
    int ch = blockIdx.x, dir = blockIdx.y;
    __shared__ __align__(16) float buf[16*32*18];
    int tid = threadIdx.x;
    int cgid = tid & 15, sp = tid >> 4;

    float w0[32], w1[32];
    {
        const float* wp = d_whP + (size_t)dir*H_*G4_ + (size_t)(sp*32)*G4_ + ch*32 + cgid*2;
        #pragma unroll
        for (int k = 0; k < 32; k++){
            float2 ww = *reinterpret_cast<const float2*>(&wp[(size_t)k*G4_]);
            w0[k] = ww.x; w1[k] = ww.y;
        }
    }
    int hl = tid >> 4, bb = tid & 15;
    int lenb = (tid < 128) ? lengths[bb] : 0;
    int hg = ch*8 + hl;

    for (int t = 0; t < T_; t++){
        const float* hprev = d_hstate + dir*(B_*H_);
        for (int i = tid; i < H_*16; i += 256){
            int k = i >> 4, b = i & 15;
            buf[i] = hprev[b*H_ + k];
        }
        __syncthreads();

        unsigned long long a0[8] = {0,0,0,0,0,0,0,0};
        unsigned long long a1[8] = {0,0,0,0,0,0,0,0};
        const unsigned long long* hbase = reinterpret_cast<const unsigned long long*>(&buf[(sp*32)*16]);
        #pragma unroll
        for (int k = 0; k < 32; k++){
            unsigned long long wA, wB;
            asm("mov.b64 %0, {%1, %1};" : "=l"(wA) : "r"(__float_as_uint(w0[k])));
            asm("mov.b64 %0, {%1, %1};" : "=l"(wB) : "r"(__float_as_uint(w1[k])));
            const unsigned long long* hv = hbase + k*8;
            #pragma unroll
            for (int j=0;j<8;j++){
                unsigned long long h = hv[j];
                asm("fma.rn.f32x2 %0, %1, %2, %0;" : "+l"(a0[j]) : "l"(h), "l"(wA));
                asm("fma.rn.f32x2 %0, %1, %2, %0;" : "+l"(a1[j]) : "l"(h), "l"(wB));
            }
        }
        __syncthreads();
        {
            float* r0 = &buf[(sp*32 + cgid*2    )*18];
            float* r1 = &buf[(sp*32 + cgid*2 + 1)*18];
            #pragma unroll
            for (int j=0;j<8;j++){
                unsigned lo,hi;
                asm("mov.b64 {%0, %1}, %2;" : "=r"(lo), "=r"(hi) : "l"(a0[j]));
                r0[2*j] = __uint_as_float(lo); r0[2*j+1] = __uint_as_float(hi);
                asm("mov.b64 {%0, %1}, %2;" : "=r"(lo), "=r"(hi) : "l"(a1[j]));
                r1[2*j] = __uint_as_float(lo); r1[2*j+1] = __uint_as_float(hi);
            }
        }
        __syncthreads();

        if (tid < 128){
            const float* gpre = (dir ? d_gpre_bw : d_gpre_fw) + (size_t)(bb*T_ + t)*G4_;
            float g4[4];
            #pragma unroll
            for (int g = 0; g < 4; g++){
                int cc = hl*4 + g;
                float s = 0.f;
                #pragma unroll
                for (int q = 0; q < 16; q++) s += buf[(q*32 + cc)*18 + bb];
                g4[g] = s + gpre[g*H_ + hg];
            }
            int idx = (dir*B_ + bb)*H_ + hg;
            float cs = d_cstate[idx], hp = d_hstate[idx];
            float cn = sigmf(g4[2] + 1.f)*cs + sigmf(g4[0])*tanhf(g4[1]);
            float hn = sigmf(g4[3])*tanhf(cn);
            bool m = (t < lenb);
            d_cstate[idx] = m ? cn : cs;
            d_hstate[idx] = m ? hn : hp;
            float ho = m ? hn : 0.f;
            if (dir == 0) d_hcat[(size_t)(bb*T_ + t)*(2*H_) + hg] = ho;
            else { int p = m ? (lenb-1-t) : t; d_hcat[(size_t)(bb*T_ + p)*(2*H_) + H_ + hg] = ho; }
        }

        __threadfence();
        __syncthreads();
        if (tid == 0){
            atomicAdd(&d_bars[t], 1u);
            while (*((volatile unsigned*)&d_bars[t]) < 128u) {}
        }
        __syncthreads();
        __threadfence();
    }
}

__global__ void k_nulllogits(const float* __restrict__ Wv, const float* __restrict__ bv){
    __shared__ float ns[H_];
    int tid = threadIdx.x;
    for (int k=tid; k<H_; k+=256) ns[k] = d_nullstate[k];
    __syncthreads();
    int v = blockIdx.x*256 + tid;
    if (v < VS_){
        float a = bv[v];
        #pragma unroll 4
        for (int k=0;k<H_;k++) a = fmaf(ns[k], Wv[(size_t)k*VS_+v], a);
        d_nulllog[v] = a;
    }
}

__global__ void k_nullreduce(){
    __shared__ float sm[1024];
    int tid = threadIdx.x;
    float m = -1e30f;
    for (int v=tid; v<VS_; v+=1024) m = fmaxf(m, d_nulllog[v]);
    sm[tid]=m; __syncthreads();
    for (int s=512;s>0;s>>=1){ if(tid<s) sm[tid]=fmaxf(sm[tid],sm[tid+s]); __syncthreads(); }
    float mx = sm[0]; __syncthreads();
    float su = 0.f;
    for (int v=tid; v<VS_; v+=1024) su += expf(d_nulllog[v]-mx);
    sm[tid]=su; __syncthreads();
    for (int s=512;s>0;s>>=1){ if(tid<s) sm[tid]+=sm[tid+s]; __syncthreads(); }
    if (tid==0){ d_nullred[0]=mx; d_nullred[1]=sm[0]; }
}

__global__ void k_emission(const int* __restrict__ sources, float* __restrict__ out){
    int bt = blockIdx.x, b = bt>>6, t = bt&63, s = threadIdx.x;   // 64
    int col = sources[b*S_+s];
    int rep = d_colmap[(size_t)b*VS_ + col];     // representative gather slot
    float l = d_glog[bt*S_ + rep];
    out[(size_t)b*(2*T_*S_) + t*S_ + s] = expf(l - d_rowmax[bt]) / d_rowsum[bt];
    out[(size_t)b*(2*T_*S_) + (T_+t)*S_ + s] = expf(d_nulllog[col]-d_nullred[0]) / d_nullred[1];
}

__global__ void k_jsoftmax(){
    int row = blockIdx.x, tid = threadIdx.x;
    float* p = d_jl + (size_t)row*J_;
    __shared__ float sm[256];
    float m = -1e30f;
    for (int j=tid; j<J_; j+=256) m = fmaxf(m, p[j]);
    sm[tid]=m; __syncthreads();
    for (int s=128;s>0;s>>=1){ if(tid<s) sm[tid]=fmaxf(sm[tid],sm[tid+s]); __syncthreads(); }
    float mx = sm[0]; __syncthreads();
    float su = 0.f;
    for (int j=tid; j<J_; j+=256) su += expf(p[j]-mx);
    sm[tid]=su; __syncthreads();
    for (int s=128;s>0;s>>=1){ if(tid<s) sm[tid]+=sm[tid+s]; __syncthreads(); }
    float inv = 1.f/sm[0]; __syncthreads();
    for (int j=tid; j<J_; j+=256) p[j] = expf(p[j]-mx)*inv;
}

__global__ void k_p0(const float* __restrict__ Wp0, const float* __restrict__ bp0){
    int gw = (blockIdx.x*blockDim.x + threadIdx.x) >> 5;
    int lane = threadIdx.x & 31;
    if (gw >= BT_) return;
    float a = 0.f;
    for (int k=lane; k<H_; k+=32) a = fmaf(d_tt[(size_t)gw*H_+k], Wp0[k], a);
    #pragma unroll
    for (int o=16;o>0;o>>=1) a += __shfl_xor_sync(0xffffffffu, a, o);
    if (lane==0) d_p0v[gw] = sigmf(a + bp0[0]);
}

__global__ void k_transition(float* __restrict__ out){
    int b = blockIdx.y;
    int idx = blockIdx.x*256 + threadIdx.x;
    if (idx >= T_*2*T_) return;
    int i = idx / (2*T_), c = idx % (2*T_);
    float tv, lv;
    if (c < T_){
        float jw = d_jl[(size_t)(b*T_+i)*J_ + (MM_ + c - i)];
        tv = jw; lv = logf(jw);
    } else {
        int j = c - T_;
        float p = d_p0v[b*T_+i];
        tv = (i==j) ? p : 0.f;
        lv = (i==j) ? logf(p) : 0.f;
    }
    float* tr  = out + (size_t)B_*2*T_*S_ + (size_t)b*(2*T_*2*T_);
    float* trl = tr + (size_t)B_*2*T_*2*T_;
    tr [i*2*T_ + c] = tv;  tr [(T_+i)*2*T_ + c] = tv;
    trl[i*2*T_ + c] = lv;  trl[(T_+i)*2*T_ + c] = lv;
}

extern "C" void kernel_launch(void* const* d_in, const int* in_sizes, int n_in,
                              void* d_out, int out_size) {
    const int*   sources = (const int*)  d_in[0];
    const int*   targets = (const int*)  d_in[1];
    const int*   tnull   = (const int*)  d_in[2];
    const int*   lengths = (const int*)  d_in[3];
    const float* emb     = (const float*)d_in[4];
    const float* nnW     = (const float*)d_in[5];
    const float* nnb     = (const float*)d_in[6];
    const float* Wx_fw   = (const float*)d_in[7];
    const float* Wh_fw   = (const float*)d_in[8];
    const float* b_fw    = (const float*)d_in[9];
    const float* Wx_bw   = (const float*)d_in[10];
    const float* Wh_bw   = (const float*)d_in[11];
    const float* b_bw    = (const float*)d_in[12];
    const float* Wproj_e = (const float*)d_in[13];
    const float* Wv      = (const float*)d_in[14];
    const float* bv      = (const float*)d_in[15];
    const float* Wproj_t = (const float*)d_in[16];
    const float* Wj      = (const float*)d_in[17];
    const float* bj      = (const float*)d_in[18];
    const float* Wp0     = (const float*)d_in[19];
    const float* bp0     = (const float*)d_in[20];
    float* out = (float*)d_out;

    float *gfw, *gbw, *xp, *xrp, *hc, *tmp, *ttp, *jl;
    __nv_bfloat16 *tsb, *wvT;
    cudaGetSymbolAddress((void**)&gfw, d_gpre_fw);
    cudaGetSymbolAddress((void**)&gbw, d_gpre_bw);
    cudaGetSymbolAddress((void**)&xp,  d_x);
    cudaGetSymbolAddress((void**)&xrp, d_xrev);
    cudaGetSymbolAddress((void**)&hc,  d_hcat);
    cudaGetSymbolAddress((void**)&tmp, d_tmpt);
    cudaGetSymbolAddress((void**)&ttp, d_tt);
    cudaGetSymbolAddress((void**)&jl,  d_jl);
    cudaGetSymbolAddress((void**)&tsb, d_tsb);
    cudaGetSymbolAddress((void**)&wvT, d_wvT);

    k_init<<<64,256>>>();
    k_srcmap_clear<<<(B_*VS_+255)/256,256>>>();
    k_srcmap_fill<<<4,256>>>(sources);
    k_embed<<<BT_,256>>>(targets, lengths, emb);
    k_nullstate<<<1,512>>>(tnull, emb, nnW, nnb);
    k_permwh<<<512,256>>>(Wh_fw, Wh_bw);
    k_cvt_wvT<<<dim3(1000,16),dim3(32,8)>>>(Wv);

    // input projections (tf32)
    tf32gemm_k<0><<<dim3(8,16),256>>>(xp,  Wx_fw, b_fw, gfw, BT_, G4_, E_);
    tf32gemm_k<0><<<dim3(8,16),256>>>(xrp, Wx_bw, b_bw, gbw, BT_, G4_, E_);

    // persistent LSTM
    k_lstm_all<<<dim3(64,2),256>>>(lengths);

    // emission: proj_e -> bf16, fused logits GEMM (no logits buffer)
    tf32gemm_bf16o_k<<<dim3(8,4),256>>>(hc, Wproj_e, tsb, BT_, H_, 2*H_);
    bf16gemm_fused_k<<<dim3(8,NCT_),256>>>(tsb, wvT, bv);
    k_rowfinal<<<BT_,256>>>();
    k_nulllogits<<<125,256>>>(Wv, bv);
    k_nullreduce<<<1,1024>>>();
    k_emission<<<BT_,64>>>(sources, out);

    // transition path
    tf32gemm_k<0><<<dim3(8,2),256>>>(hc, Wproj_t, nullptr, tmp, BT_, E_, 2*H_);
    tf32gemm_k<1><<<dim3(8,4),256>>>(tmp, nnW, nnb, ttp, BT_, H_, E_);
    sgemm_k<0><<<dim3(2,16),256>>>(ttp, Wj, bj, jl, BT_, J_, H_);
    k_jsoftmax<<<BT_,256>>>();
    k_p0<<<128,256>>>(Wp0, bp0);
    k_transition<<<dim3(32,16),256>>>(out);
}